// round 11
// baseline (speedup 1.0000x reference)
#include <cuda_runtime.h>
#include <cuda_bf16.h>
#include <cuda_fp16.h>
#include <cstdint>

// Problem constants (match reference_code)
#define NN 50000      // nodes
#define EE 800000     // edges
#define IN_F 128
#define DD 64
#define HH 4
#define HD 256        // H*D
#define NEG_SLOPE 0.2f

#define SCAN_CHUNK 4096
#define SCAN_BLOCKS ((NN + SCAN_CHUNK - 1) / SCAN_CHUNK)   // 13

// ---------------------------------------------------------------------------
// Scratch (static __device__ arrays — no allocation allowed)
// ---------------------------------------------------------------------------
__device__ __half   g_feat_h[(size_t)NN * HD]; // projected features [N,256] fp16
__device__ float    g_h[(size_t)NN * HD];      // layer io buffer (fp32)
__device__ float    g_el[(size_t)NN * HH];
__device__ float    g_er[(size_t)NN * HH];
__device__ int      g_rowptr[NN + 1];
__device__ int      g_cur[NN];
__device__ int      g_csr[EE];                 // src per CSR slot (sorted by dst)
__device__ int      g_bsum[SCAN_BLOCKS];       // scan phase-1 block totals
// W in mma-fragment order, all 4 layers: uint4 = {bh0,bh1,bl0,bl1}
// layer0 (K=128): 8192 uint4; layers1-3 (K=64): 4096 uint4 each
__device__ uint4    g_Wf[8192 + 3 * 4096];

// ---------------------------------------------------------------------------
// CSR build: (zero fused into split) -> histogram -> scan1 -> scan2 -> scatter
// ---------------------------------------------------------------------------
__global__ void hist_k(const int* __restrict__ dst) {
    int e = blockIdx.x * blockDim.x + threadIdx.x;
    if (e < EE) atomicAdd(&g_cur[dst[e]], 1);
}

// Phase 1: each block locally exclusive-scans its 4096-chunk of g_cur into
// g_rowptr (local values), re-zeros g_cur, writes chunk total to g_bsum.
__global__ void __launch_bounds__(1024) scan1_k() {
    __shared__ int ws[32];
    int t = threadIdx.x, lane = t & 31, wid = t >> 5;
    int i0 = blockIdx.x * SCAN_CHUNK + t * 4;
    int4 v = make_int4(0, 0, 0, 0);
    if (i0 < NN) {
        v = *(const int4*)&g_cur[i0];
        *(int4*)&g_cur[i0] = make_int4(0, 0, 0, 0);
    }
    int tsum = v.x + v.y + v.z + v.w;
    int x = tsum;
    #pragma unroll
    for (int o = 1; o < 32; o <<= 1) {
        int y = __shfl_up_sync(0xffffffffu, x, o);
        if (lane >= o) x += y;
    }
    if (lane == 31) ws[wid] = x;
    __syncthreads();
    if (wid == 0) {
        int y = ws[lane];
        #pragma unroll
        for (int o = 1; o < 32; o <<= 1) {
            int z = __shfl_up_sync(0xffffffffu, y, o);
            if (lane >= o) y += z;
        }
        ws[lane] = y;
    }
    __syncthreads();
    int excl = x - tsum + (wid ? ws[wid - 1] : 0);
    if (i0 < NN) {
        g_rowptr[i0]     = excl;
        g_rowptr[i0 + 1] = excl + v.x;
        g_rowptr[i0 + 2] = excl + v.x + v.y;
        g_rowptr[i0 + 3] = excl + v.x + v.y + v.z;
    }
    if (t == 1023) g_bsum[blockIdx.x] = ws[31];
}

// Phase 2: each block adds the prefix of earlier block totals to its chunk.
__global__ void __launch_bounds__(1024) scan2_k() {
    __shared__ int s_off, s_tot;
    int t = threadIdx.x, b = blockIdx.x;
    if (t == 0) {
        int off = 0, tot = 0;
        #pragma unroll
        for (int j = 0; j < SCAN_BLOCKS; j++) {
            int v = g_bsum[j];
            if (j < b) off += v;
            tot += v;
        }
        s_off = off; s_tot = tot;
    }
    __syncthreads();
    int off = s_off;
    int i0 = b * SCAN_CHUNK + t * 4;
    if (off != 0 && i0 < NN) {
        int4 r = *(int4*)&g_rowptr[i0];
        r.x += off; r.y += off; r.z += off; r.w += off;
        *(int4*)&g_rowptr[i0] = r;
    }
    if (b == 0 && t == 0) g_rowptr[NN] = s_tot;
}

__global__ void scatter_k(const int* __restrict__ src, const int* __restrict__ dst) {
    int e = blockIdx.x * blockDim.x + threadIdx.x;
    if (e < EE) {
        int d = dst[e];
        int pos = g_rowptr[d] + atomicAdd(&g_cur[d], 1);
        g_csr[pos] = src[e];
    }
}

// ---------------------------------------------------------------------------
// bf16 split helpers
// ---------------------------------------------------------------------------
__device__ __forceinline__ void bf16_split(float v, __nv_bfloat16& h, __nv_bfloat16& l) {
    h = __float2bfloat16_rn(v);
    l = __float2bfloat16_rn(v - __bfloat162float(h));
}
__device__ __forceinline__ uint32_t pack_bf16(__nv_bfloat16 lo, __nv_bfloat16 hi) {
    __nv_bfloat162 p = __halves2bfloat162(lo, hi);
    return *reinterpret_cast<uint32_t*>(&p);
}

// Split ALL layer weights into fragment-packed uint4 layout, one launch,
// AND zero g_cur (fused; saves a launch).
// Fragment row r = ks*4 + q; element (r, n) = {bh0, bh1, bl0, bl1} where
//   bh0/bl0 = hi/lo of (W[2*k2a], W[2*k2a+1])  k2a = ks*8 + q
//   bh1/bl1 = hi/lo of (W[2*k2b], W[2*k2b+1])  k2b = ks*8 + 4 + q
__global__ void split_zero_k(const float* __restrict__ W1,
                             const float* __restrict__ Whp)
{
    int tid = blockIdx.x * blockDim.x + threadIdx.x;
    if (tid >= 20480) {
        int z = tid - 20480;
        if (z < NN) g_cur[z] = 0;
        return;
    }
    const float* W;
    int r, n, off;
    if (tid < 8192) {                       // layer 0, K=128, 32 rows
        W = W1; r = tid >> 8; n = tid & 255; off = 0;
    } else {
        int t2 = tid - 8192;
        int layer = t2 >> 12;               // 0..2
        W = Whp + (size_t)layer * DD * HD;
        r = (t2 & 4095) >> 8; n = t2 & 255;
        off = 8192 + layer * 4096;
    }
    int ks = r >> 2, q = r & 3;
    int k2a = ks * 8 + q;
    int k2b = ks * 8 + 4 + q;
    float wa0 = W[(2 * k2a) * 256 + n],     wa1 = W[(2 * k2a + 1) * 256 + n];
    float wb0 = W[(2 * k2b) * 256 + n],     wb1 = W[(2 * k2b + 1) * 256 + n];
    __nv_bfloat16 ha0, la0, ha1, la1, hb0, lb0, hb1, lb1;
    bf16_split(wa0, ha0, la0);
    bf16_split(wa1, ha1, la1);
    bf16_split(wb0, hb0, lb0);
    bf16_split(wb1, hb1, lb1);
    uint4 o;
    o.x = pack_bf16(ha0, ha1);
    o.y = pack_bf16(hb0, hb1);
    o.z = pack_bf16(la0, la1);
    o.w = pack_bf16(lb0, lb1);
    g_Wf[off + r * 256 + n] = o;
}

// ---------------------------------------------------------------------------
// bf16 3-term tensor-core GEMM + fused attention coefficients.
// D = Ah*Wh + Ah*Wl + Al*Wh. W staged in smem in fragment-packed uint4 form:
// B fragment = ONE LDS.128 per (ks, j) (vs 4 LDS.32).
// Block: 256 thr = 8 warps, 2(M) x 4(N); warp tile m32 x n64 (1 head/warp).
// WS4 = 258 (≡ 2 mod 8) -> each 8-lane LDS.128 phase hits 8 distinct bank
// groups: structural 4-cycle floor, no extra conflicts.
// ---------------------------------------------------------------------------
__device__ __forceinline__ void mma_bf16(float* c, const uint32_t* a,
                                         uint32_t b0, uint32_t b1)
{
    asm volatile(
        "mma.sync.aligned.m16n8k16.row.col.f32.bf16.bf16.f32 "
        "{%0,%1,%2,%3}, {%4,%5,%6,%7}, {%8,%9}, {%0,%1,%2,%3};"
        : "+f"(c[0]), "+f"(c[1]), "+f"(c[2]), "+f"(c[3])
        : "r"(a[0]), "r"(a[1]), "r"(a[2]), "r"(a[3]), "r"(b0), "r"(b1));
}

template <int K>
__global__ void __launch_bounds__(256) gemm_mma_k(
    const float* __restrict__ hin, int wf_off,
    const float* __restrict__ al, const float* __restrict__ ar)
{
    constexpr int K2  = K / 2;
    constexpr int ASp = K2 + 4;   // ≡ 4 (mod 32): A frag loads conflict-free
    constexpr int WS4 = 258;      // uint4 stride, ≡ 2 (mod 8)
    constexpr int NW4 = K / 4;    // fragment rows (ks*4+q)
    extern __shared__ uint32_t smu[];
    uint32_t* sAh = smu;                         // 64*ASp
    uint32_t* sAl = sAh + 64 * ASp;              // 64*ASp
    uint4*    sW4 = (uint4*)(sAl + 64 * ASp);    // NW4*WS4 uint4 (16B aligned)

    int t = threadIdx.x, lane = t & 31, wid = t >> 5;
    int wm = wid >> 2, wn = wid & 3;     // warp M-row, warp N-col (= head)
    int g = lane >> 2, q = lane & 3;     // groupID (row), quad lane
    int n0 = blockIdx.x * 64;

    // Stage A as packed bf16 hi/lo k-pairs; zero-fill rows >= NN
    for (int idx = t; idx < 64 * K2; idx += 256) {
        int r = idx / K2, k2 = idx % K2;
        float v0 = 0.f, v1 = 0.f;
        if (n0 + r < NN) {
            float2 vv = *(const float2*)&hin[(size_t)(n0 + r) * K + 2 * k2];
            v0 = vv.x; v1 = vv.y;
        }
        __nv_bfloat16 h0, l0, h1, l1;
        bf16_split(v0, h0, l0);
        bf16_split(v1, h1, l1);
        sAh[r * ASp + k2] = pack_bf16(h0, h1);
        sAl[r * ASp + k2] = pack_bf16(l0, l1);
    }
    // Stage W fragments (uint4 copies)
    for (int idx = t; idx < NW4 * 256; idx += 256) {
        int r = idx >> 8, n = idx & 255;
        sW4[r * WS4 + n] = g_Wf[wf_off + idx];
    }
    __syncthreads();

    float c_[2][8][4];
    #pragma unroll
    for (int i = 0; i < 2; i++)
        #pragma unroll
        for (int j = 0; j < 8; j++)
            #pragma unroll
            for (int r = 0; r < 4; r++) c_[i][j][r] = 0.f;

    for (int ks = 0; ks < K / 16; ks++) {
        int k2b = ks * 8;
        uint32_t ah[2][4], alr[2][4];
        #pragma unroll
        for (int i = 0; i < 2; i++) {
            int r = wm * 32 + i * 16 + g;
            ah[i][0]  = sAh[r * ASp + k2b + q];
            ah[i][1]  = sAh[(r + 8) * ASp + k2b + q];
            ah[i][2]  = sAh[r * ASp + k2b + 4 + q];
            ah[i][3]  = sAh[(r + 8) * ASp + k2b + 4 + q];
            alr[i][0] = sAl[r * ASp + k2b + q];
            alr[i][1] = sAl[(r + 8) * ASp + k2b + q];
            alr[i][2] = sAl[r * ASp + k2b + 4 + q];
            alr[i][3] = sAl[(r + 8) * ASp + k2b + 4 + q];
        }
        const uint4* wrow = &sW4[(ks * 4 + q) * WS4 + wn * 64 + g];
        #pragma unroll
        for (int j = 0; j < 8; j++) {
            uint4 f = wrow[j * 8];
            #pragma unroll
            for (int i = 0; i < 2; i++) {
                mma_bf16(c_[i][j], ah[i],  f.x, f.y);
                mma_bf16(c_[i][j], ah[i],  f.z, f.w);
                mma_bf16(c_[i][j], alr[i], f.x, f.y);
            }
        }
    }

    // Epilogue: store feat (fp16), fused el/er (this warp's head = wn, fp32)
    float alv[8][2], arv[8][2];
    #pragma unroll
    for (int j = 0; j < 8; j++) {
        int col = wn * 64 + j * 8 + 2 * q;
        alv[j][0] = al[col]; alv[j][1] = al[col + 1];
        arv[j][0] = ar[col]; arv[j][1] = ar[col + 1];
    }
    #pragma unroll
    for (int i = 0; i < 2; i++) {
        int rtop = n0 + wm * 32 + i * 16 + g;
        int rbot = rtop + 8;
        float plt = 0.f, prt = 0.f, plb = 0.f, prb = 0.f;
        #pragma unroll
        for (int j = 0; j < 8; j++) {
            int cb = wn * 64 + j * 8 + 2 * q;
            if (rtop < NN)
                *(__half2*)&g_feat_h[(size_t)rtop * HD + cb] =
                    __floats2half2_rn(c_[i][j][0], c_[i][j][1]);
            if (rbot < NN)
                *(__half2*)&g_feat_h[(size_t)rbot * HD + cb] =
                    __floats2half2_rn(c_[i][j][2], c_[i][j][3]);
            plt += c_[i][j][0] * alv[j][0] + c_[i][j][1] * alv[j][1];
            prt += c_[i][j][0] * arv[j][0] + c_[i][j][1] * arv[j][1];
            plb += c_[i][j][2] * alv[j][0] + c_[i][j][3] * alv[j][1];
            prb += c_[i][j][2] * arv[j][0] + c_[i][j][3] * arv[j][1];
        }
        #pragma unroll
        for (int o = 1; o <= 2; o <<= 1) {
            plt += __shfl_xor_sync(0xffffffffu, plt, o);
            prt += __shfl_xor_sync(0xffffffffu, prt, o);
            plb += __shfl_xor_sync(0xffffffffu, plb, o);
            prb += __shfl_xor_sync(0xffffffffu, prb, o);
        }
        if (q == 0) {
            if (rtop < NN) { g_el[rtop * HH + wn] = plt; g_er[rtop * HH + wn] = prt; }
            if (rbot < NN) { g_el[rbot * HH + wn] = plb; g_er[rbot * HH + wn] = prb; }
        }
    }
}

// ---------------------------------------------------------------------------
// Warp-per-node edge softmax + aggregation (R8 form — best measured).
// ---------------------------------------------------------------------------
__device__ __forceinline__ float lrelu(float e) {
    return e > 0.f ? e : NEG_SLOPE * e;
}

template <bool MEAN>
__global__ void __launch_bounds__(256) edge_agg_w(
    const float* __restrict__ b, float* __restrict__ out)
{
    __shared__ float s_w_all[8][HH][33];
    __shared__ int   s_src_all[8][32];

    int t = threadIdx.x, lane = t & 31, wid = t >> 5;
    int n = blockIdx.x * 8 + wid;
    if (n >= NN) return;

    float (*s_w)[33] = s_w_all[wid];
    int* s_src = s_src_all[wid];

    int rb  = g_rowptr[n];
    int deg = g_rowptr[n + 1] - rb;

    int h = lane >> 3;
    float acc[8];
    #pragma unroll
    for (int i = 0; i < 8; i++) acc[i] = 0.f;

    const uint4* fb = (const uint4*)g_feat_h;

    if (deg > 0 && deg <= 32) {
        float4 er4 = *(const float4*)(g_er + n * HH);
        float e0 = -1e30f, e1 = -1e30f, e2 = -1e30f, e3 = -1e30f;
        if (lane < deg) {
            int sn = g_csr[rb + lane];
            s_src[lane] = sn;
            float4 el4 = *(const float4*)(g_el + sn * HH);
            e0 = lrelu(el4.x + er4.x);
            e1 = lrelu(el4.y + er4.y);
            e2 = lrelu(el4.z + er4.z);
            e3 = lrelu(el4.w + er4.w);
        }
        float m0 = e0, m1 = e1, m2 = e2, m3 = e3;
        #pragma unroll
        for (int o = 16; o; o >>= 1) {
            m0 = fmaxf(m0, __shfl_xor_sync(0xffffffffu, m0, o));
            m1 = fmaxf(m1, __shfl_xor_sync(0xffffffffu, m1, o));
            m2 = fmaxf(m2, __shfl_xor_sync(0xffffffffu, m2, o));
            m3 = fmaxf(m3, __shfl_xor_sync(0xffffffffu, m3, o));
        }
        float w0 = 0.f, w1 = 0.f, w2 = 0.f, w3 = 0.f;
        if (lane < deg) {
            w0 = __expf(e0 - m0);
            w1 = __expf(e1 - m1);
            w2 = __expf(e2 - m2);
            w3 = __expf(e3 - m3);
        }
        float s0 = w0, s1 = w1, s2 = w2, s3 = w3;
        #pragma unroll
        for (int o = 16; o; o >>= 1) {
            s0 += __shfl_xor_sync(0xffffffffu, s0, o);
            s1 += __shfl_xor_sync(0xffffffffu, s1, o);
            s2 += __shfl_xor_sync(0xffffffffu, s2, o);
            s3 += __shfl_xor_sync(0xffffffffu, s3, o);
        }
        if (lane < deg) {
            s_w[0][lane] = w0 / s0;
            s_w[1][lane] = w1 / s1;
            s_w[2][lane] = w2 / s2;
            s_w[3][lane] = w3 / s3;
        }
        __syncwarp();

        for (int j = 0; j < deg; j++) {
            int   sn = s_src[j];
            float w  = s_w[h][j];
            uint4 f  = fb[(size_t)sn * 32 + lane];
            float2 p0 = __half22float2(*(const __half2*)&f.x);
            float2 p1 = __half22float2(*(const __half2*)&f.y);
            float2 p2 = __half22float2(*(const __half2*)&f.z);
            float2 p3 = __half22float2(*(const __half2*)&f.w);
            acc[0] += w * p0.x; acc[1] += w * p0.y;
            acc[2] += w * p1.x; acc[3] += w * p1.y;
            acc[4] += w * p2.x; acc[5] += w * p2.y;
            acc[6] += w * p3.x; acc[7] += w * p3.y;
        }
    } else if (deg > 32) {
        float er_h = g_er[n * HH + h];
        float m = -1e30f;
        for (int j = 0; j < deg; j++) {
            int sn = g_csr[rb + j];
            m = fmaxf(m, lrelu(g_el[sn * HH + h] + er_h));
        }
        float s = 0.f;
        for (int j = 0; j < deg; j++) {
            int sn = g_csr[rb + j];
            s += __expf(lrelu(g_el[sn * HH + h] + er_h) - m);
        }
        float inv = 1.0f / s;
        for (int j = 0; j < deg; j++) {
            int sn = g_csr[rb + j];
            float w = __expf(lrelu(g_el[sn * HH + h] + er_h) - m) * inv;
            uint4 f = fb[(size_t)sn * 32 + lane];
            float2 p0 = __half22float2(*(const __half2*)&f.x);
            float2 p1 = __half22float2(*(const __half2*)&f.y);
            float2 p2 = __half22float2(*(const __half2*)&f.z);
            float2 p3 = __half22float2(*(const __half2*)&f.w);
            acc[0] += w * p0.x; acc[1] += w * p0.y;
            acc[2] += w * p1.x; acc[3] += w * p1.y;
            acc[4] += w * p2.x; acc[5] += w * p2.y;
            acc[6] += w * p3.x; acc[7] += w * p3.y;
        }
    }

    if (MEAN) {
        #pragma unroll
        for (int o = 8; o <= 16; o <<= 1)
            #pragma unroll
            for (int i = 0; i < 8; i++)
                acc[i] += __shfl_down_sync(0xffffffffu, acc[i], o);
        if (lane < 8) {
            int d0 = lane * 8;
            float r[8];
            #pragma unroll
            for (int i = 0; i < 8; i++) {
                int d = d0 + i;
                r[i] = 0.25f * (acc[i] + b[d] + b[DD + d] + b[2 * DD + d] + b[3 * DD + d]);
            }
            float4* o4 = (float4*)(out + (size_t)n * DD + d0);
            o4[0] = make_float4(r[0], r[1], r[2], r[3]);
            o4[1] = make_float4(r[4], r[5], r[6], r[7]);
        }
    } else {
        int d0 = lane * 8;
        float r[8];
        #pragma unroll
        for (int i = 0; i < 8; i++) r[i] = acc[i] + b[d0 + i];
        float4* o4 = (float4*)(out + (size_t)n * HD + d0);
        o4[0] = make_float4(r[0], r[1], r[2], r[3]);
        o4[1] = make_float4(r[4], r[5], r[6], r[7]);
    }
}

// ---------------------------------------------------------------------------
// Final Linear(256->64) + LayerNorm (no affine). 16 nodes/block, 64 threads.
// ---------------------------------------------------------------------------
__global__ void __launch_bounds__(64) final_ln_k(
    const float* __restrict__ hin, const float* __restrict__ Wo,
    const float* __restrict__ bo, float* __restrict__ out)
{
    constexpr int NB = 16;
    constexpr int K4 = HD / 4;               // 64
    __shared__ float4 sh4[NB * K4];          // 16 KB
    __shared__ float so[NB * DD];            // 4 KB
    __shared__ float mu_s[NB], rs_s[NB];
    int t = threadIdx.x;
    int n0 = blockIdx.x * NB;

    const float4* hin4 = (const float4*)(hin + (size_t)n0 * HD);
    for (int idx = t; idx < NB * K4; idx += 64)
        sh4[idx] = hin4[idx];
    __syncthreads();

    float acc[NB];
    #pragma unroll
    for (int i = 0; i < NB; i++) acc[i] = 0.f;
    float bv = bo[t];

    for (int k4 = 0; k4 < K4; k4++) {
        int k = k4 * 4;
        float w0 = __ldg(&Wo[(k + 0) * DD + t]);
        float w1 = __ldg(&Wo[(k + 1) * DD + t]);
        float w2 = __ldg(&Wo[(k + 2) * DD + t]);
        float w3 = __ldg(&Wo[(k + 3) * DD + t]);
        #pragma unroll
        for (int i = 0; i < NB; i++) {
            float4 s = sh4[i * K4 + k4];
            acc[i] += s.x * w0;
            acc[i] += s.y * w1;
            acc[i] += s.z * w2;
            acc[i] += s.w * w3;
        }
    }

    #pragma unroll
    for (int i = 0; i < NB; i++) so[i * DD + t] = acc[i] + bv;
    __syncthreads();

    if (t < NB) {
        float s = 0.f;
        for (int j = 0; j < DD; j++) s += so[t * DD + j];
        float mu = s * (1.0f / DD);
        float s2 = 0.f;
        for (int j = 0; j < DD; j++) {
            float d = so[t * DD + j] - mu;
            s2 += d * d;
        }
        mu_s[t] = mu;
        rs_s[t] = rsqrtf(s2 * (1.0f / DD) + 1e-5f);
    }
    __syncthreads();

    #pragma unroll
    for (int i = 0; i < NB; i++)
        out[(size_t)(n0 + i) * DD + t] = (so[i * DD + t] - mu_s[i]) * rs_s[i];
}

// ---------------------------------------------------------------------------
// Launch: inputs (metadata order):
// 0 in_feat[N,128] 1 src[E] 2 dst[E] 3 W1[128,256] 4 al1[4,64] 5 ar1[4,64]
// 6 b1[256] 7 Wh[3,64,256] 8 alh[3,4,64] 9 arh[3,4,64] 10 bh[3,256]
// 11 Wo[256,64] 12 bo[64]  -> out float32 [N,64]
// ---------------------------------------------------------------------------
extern "C" void kernel_launch(void* const* d_in, const int* in_sizes, int n_in,
                              void* d_out, int out_size)
{
    const float* in_feat = (const float*)d_in[0];
    const int*   src     = (const int*)d_in[1];
    const int*   dst     = (const int*)d_in[2];
    const float* W1      = (const float*)d_in[3];
    const float* al1     = (const float*)d_in[4];
    const float* ar1     = (const float*)d_in[5];
    const float* b1      = (const float*)d_in[6];
    const float* Whp     = (const float*)d_in[7];
    const float* alh     = (const float*)d_in[8];
    const float* arh     = (const float*)d_in[9];
    const float* bh      = (const float*)d_in[10];
    const float* Wo      = (const float*)d_in[11];
    const float* bo      = (const float*)d_in[12];
    float* out = (float*)d_out;

    float* g_h_ptr;
    cudaGetSymbolAddress((void**)&g_h_ptr, g_h);

    // smem bytes: 2*64*ASp*4 + (K/4)*WS4*16
    const int SMEM1 = 2 * 64 * (IN_F / 2 + 4) * 4 + (IN_F / 4) * 258 * 16; // 166912
    const int SMEMH = 2 * 64 * (DD / 2 + 4) * 4 + (DD / 4) * 258 * 16;     //  84480
    cudaFuncSetAttribute(gemm_mma_k<IN_F>,
                         cudaFuncAttributeMaxDynamicSharedMemorySize, SMEM1);
    cudaFuncSetAttribute(gemm_mma_k<DD>,
                         cudaFuncAttributeMaxDynamicSharedMemorySize, SMEMH);

    // Weight split (all layers) + g_cur zeroing, one launch.
    // 20480 split threads + 50000 zero threads = 70480 -> 276 blocks
    split_zero_k<<<(20480 + NN + 255) / 256, 256>>>(W1, Whp);

    // CSR build (parallel 2-phase scan)
    hist_k<<<(EE + 255) / 256, 256>>>(dst);
    scan1_k<<<SCAN_BLOCKS, 1024>>>();
    scan2_k<<<SCAN_BLOCKS, 1024>>>();
    scatter_k<<<(EE + 255) / 256, 256>>>(src, dst);

    const int GMMA = (NN + 63) / 64;   // 782 blocks
    const int GAGG = (NN + 7) / 8;     // 6250 blocks (8 nodes/block)

    // layer wf offsets (uint4 units)
    const int WF0 = 0, WF1 = 8192, WF2 = 8192 + 4096, WF3 = 8192 + 2 * 4096;

    // Layer 1: conv1 (K=128), mean over heads -> g_h[N,64]
    gemm_mma_k<IN_F><<<GMMA, 256, SMEM1>>>(in_feat, WF0, al1, ar1);
    edge_agg_w<true><<<GAGG, 256>>>(b1, g_h_ptr);

    // Hidden layers 0,1 (mean)
    gemm_mma_k<DD><<<GMMA, 256, SMEMH>>>(g_h_ptr, WF1, alh + 0 * HD, arh + 0 * HD);
    edge_agg_w<true><<<GAGG, 256>>>(bh + 0 * HD, g_h_ptr);
    gemm_mma_k<DD><<<GMMA, 256, SMEMH>>>(g_h_ptr, WF2, alh + 1 * HD, arh + 1 * HD);
    edge_agg_w<true><<<GAGG, 256>>>(bh + 1 * HD, g_h_ptr);

    // Hidden layer 2 (full [N,H,D] output)
    gemm_mma_k<DD><<<GMMA, 256, SMEMH>>>(g_h_ptr, WF3, alh + 2 * HD, arh + 2 * HD);
    edge_agg_w<false><<<GAGG, 256>>>(bh + 2 * HD, g_h_ptr);

    // Final linear + LayerNorm -> d_out
    final_ln_k<<<NN / 16, 64>>>(g_h_ptr, Wo, bo, out);
}

// round 12
// speedup vs baseline: 1.0378x; 1.0378x over previous
#include <cuda_runtime.h>
#include <cuda_bf16.h>
#include <cuda_fp16.h>
#include <cstdint>

// Problem constants (match reference_code)
#define NN 50000      // nodes
#define EE 800000     // edges
#define IN_F 128
#define DD 64
#define HH 4
#define HD 256        // H*D
#define NEG_SLOPE 0.2f

#define SCAN_CHUNK 4096
#define SCAN_BLOCKS ((NN + SCAN_CHUNK - 1) / SCAN_CHUNK)   // 13

// ---------------------------------------------------------------------------
// Scratch (static __device__ arrays — no allocation allowed)
// ---------------------------------------------------------------------------
__device__ __half   g_feat_h[(size_t)NN * HD]; // projected features [N,256] fp16
__device__ float    g_h[(size_t)NN * HD];      // layer io buffer (fp32)
__device__ float    g_el[(size_t)NN * HH];
__device__ float    g_er[(size_t)NN * HH];
__device__ int      g_rowptr[NN + 1];
__device__ int      g_cur[NN];
__device__ int      g_csr[EE];                 // src per CSR slot (sorted by dst)
__device__ int      g_bsum[SCAN_BLOCKS];       // scan phase-1 block totals
// W bf16 hi/lo, k-pairs packed, ALL layers: L0 64*256, L1-3 each 32*256
__device__ uint32_t g_Wph[16384 + 3 * 8192];
__device__ uint32_t g_Wpl[16384 + 3 * 8192];

// ---------------------------------------------------------------------------
// CSR build: (zero fused into split) -> histogram -> scan1 -> scan2 -> scatter
// ---------------------------------------------------------------------------
__global__ void hist_k(const int* __restrict__ dst) {
    int e = blockIdx.x * blockDim.x + threadIdx.x;
    if (e < EE) atomicAdd(&g_cur[dst[e]], 1);
}

// Phase 1: each block locally exclusive-scans its 4096-chunk of g_cur into
// g_rowptr (local values), re-zeros g_cur, writes chunk total to g_bsum.
__global__ void __launch_bounds__(1024) scan1_k() {
    __shared__ int ws[32];
    int t = threadIdx.x, lane = t & 31, wid = t >> 5;
    int i0 = blockIdx.x * SCAN_CHUNK + t * 4;
    int4 v = make_int4(0, 0, 0, 0);
    if (i0 < NN) {
        v = *(const int4*)&g_cur[i0];
        *(int4*)&g_cur[i0] = make_int4(0, 0, 0, 0);
    }
    int tsum = v.x + v.y + v.z + v.w;
    int x = tsum;
    #pragma unroll
    for (int o = 1; o < 32; o <<= 1) {
        int y = __shfl_up_sync(0xffffffffu, x, o);
        if (lane >= o) x += y;
    }
    if (lane == 31) ws[wid] = x;
    __syncthreads();
    if (wid == 0) {
        int y = ws[lane];
        #pragma unroll
        for (int o = 1; o < 32; o <<= 1) {
            int z = __shfl_up_sync(0xffffffffu, y, o);
            if (lane >= o) y += z;
        }
        ws[lane] = y;
    }
    __syncthreads();
    int excl = x - tsum + (wid ? ws[wid - 1] : 0);
    if (i0 < NN) {
        g_rowptr[i0]     = excl;
        g_rowptr[i0 + 1] = excl + v.x;
        g_rowptr[i0 + 2] = excl + v.x + v.y;
        g_rowptr[i0 + 3] = excl + v.x + v.y + v.z;
    }
    if (t == 1023) g_bsum[blockIdx.x] = ws[31];
}

// Phase 2: each block adds the prefix of earlier block totals to its chunk.
__global__ void __launch_bounds__(1024) scan2_k() {
    __shared__ int s_off, s_tot;
    int t = threadIdx.x, b = blockIdx.x;
    if (t == 0) {
        int off = 0, tot = 0;
        #pragma unroll
        for (int j = 0; j < SCAN_BLOCKS; j++) {
            int v = g_bsum[j];
            if (j < b) off += v;
            tot += v;
        }
        s_off = off; s_tot = tot;
    }
    __syncthreads();
    int off = s_off;
    int i0 = b * SCAN_CHUNK + t * 4;
    if (off != 0 && i0 < NN) {
        int4 r = *(int4*)&g_rowptr[i0];
        r.x += off; r.y += off; r.z += off; r.w += off;
        *(int4*)&g_rowptr[i0] = r;
    }
    if (b == 0 && t == 0) g_rowptr[NN] = s_tot;
}

__global__ void scatter_k(const int* __restrict__ src, const int* __restrict__ dst) {
    int e = blockIdx.x * blockDim.x + threadIdx.x;
    if (e < EE) {
        int d = dst[e];
        int pos = g_rowptr[d] + atomicAdd(&g_cur[d], 1);
        g_csr[pos] = src[e];
    }
}

// ---------------------------------------------------------------------------
// bf16 split helpers
// ---------------------------------------------------------------------------
__device__ __forceinline__ void bf16_split(float v, __nv_bfloat16& h, __nv_bfloat16& l) {
    h = __float2bfloat16_rn(v);
    l = __float2bfloat16_rn(v - __bfloat162float(h));
}
__device__ __forceinline__ uint32_t pack_bf16(__nv_bfloat16 lo, __nv_bfloat16 hi) {
    __nv_bfloat162 p = __halves2bfloat162(lo, hi);
    return *reinterpret_cast<uint32_t*>(&p);
}

// Split ALL layer weights (k-pair packed hi/lo, R10 layout), one launch,
// AND zero g_cur (fused).
__global__ void split_zero_k(const float* __restrict__ W1,
                             const float* __restrict__ Whp)
{
    int tid = blockIdx.x * blockDim.x + threadIdx.x;
    if (tid >= 40960) {
        int z = tid - 40960;
        if (z < NN) g_cur[z] = 0;
        return;
    }
    const float* W;
    int local, off;
    if (tid < 16384) {                      // layer 0, K2=64
        W = W1; local = tid; off = 0;
    } else {
        int t2 = tid - 16384;
        int layer = t2 >> 13;               // 0..2
        W = Whp + (size_t)layer * DD * HD;
        local = t2 & 8191;
        off = 16384 + layer * 8192;
    }
    int k2 = local >> 8, n = local & 255;
    float w0 = W[(2 * k2) * 256 + n];
    float w1 = W[(2 * k2 + 1) * 256 + n];
    __nv_bfloat16 h0, l0, h1, l1;
    bf16_split(w0, h0, l0);
    bf16_split(w1, h1, l1);
    g_Wph[off + local] = pack_bf16(h0, h1);
    g_Wpl[off + local] = pack_bf16(l0, l1);
}

// ---------------------------------------------------------------------------
// bf16 3-term tensor-core GEMM + fused attention coefficients (R10 form:
// smem-staged W, LDS.32 fragments — best measured).
// D = Ah*Wh + Ah*Wl + Al*Wh.
// Block: 256 thr = 8 warps, 2(M) x 4(N); warp tile m32 x n64 (1 head/warp).
// ---------------------------------------------------------------------------
__device__ __forceinline__ void mma_bf16(float* c, const uint32_t* a,
                                         uint32_t b0, uint32_t b1)
{
    asm volatile(
        "mma.sync.aligned.m16n8k16.row.col.f32.bf16.bf16.f32 "
        "{%0,%1,%2,%3}, {%4,%5,%6,%7}, {%8,%9}, {%0,%1,%2,%3};"
        : "+f"(c[0]), "+f"(c[1]), "+f"(c[2]), "+f"(c[3])
        : "r"(a[0]), "r"(a[1]), "r"(a[2]), "r"(a[3]), "r"(b0), "r"(b1));
}

template <int K>
__global__ void __launch_bounds__(256) gemm_mma_k(
    const float* __restrict__ hin, int w_off,
    const float* __restrict__ al, const float* __restrict__ ar)
{
    constexpr int K2  = K / 2;
    constexpr int ASp = K2 + 4;   // ≡ 4 (mod 32): A frag loads conflict-free
    constexpr int WSp = 264;      // ≡ 8 (mod 32): B frag loads conflict-free
    extern __shared__ uint32_t smu[];
    uint32_t* sAh = smu;                         // 64*ASp
    uint32_t* sAl = sAh + 64 * ASp;              // 64*ASp
    uint32_t* sWh = sAl + 64 * ASp;              // K2*WSp
    uint32_t* sWl = sWh + K2 * WSp;              // K2*WSp

    int t = threadIdx.x, lane = t & 31, wid = t >> 5;
    int wm = wid >> 2, wn = wid & 3;     // warp M-row, warp N-col (= head)
    int g = lane >> 2, q = lane & 3;     // groupID (row), quad lane
    int n0 = blockIdx.x * 64;

    // Stage A as packed bf16 hi/lo k-pairs; zero-fill rows >= NN
    for (int idx = t; idx < 64 * K2; idx += 256) {
        int r = idx / K2, k2 = idx % K2;
        float v0 = 0.f, v1 = 0.f;
        if (n0 + r < NN) {
            float2 vv = *(const float2*)&hin[(size_t)(n0 + r) * K + 2 * k2];
            v0 = vv.x; v1 = vv.y;
        }
        __nv_bfloat16 h0, l0, h1, l1;
        bf16_split(v0, h0, l0);
        bf16_split(v1, h1, l1);
        sAh[r * ASp + k2] = pack_bf16(h0, h1);
        sAl[r * ASp + k2] = pack_bf16(l0, l1);
    }
    // Stage full W (hi/lo)
    for (int idx = t; idx < K2 * 256; idx += 256) {
        int k2 = idx >> 8, n = idx & 255;
        sWh[k2 * WSp + n] = g_Wph[w_off + idx];
        sWl[k2 * WSp + n] = g_Wpl[w_off + idx];
    }
    __syncthreads();

    float c_[2][8][4];
    #pragma unroll
    for (int i = 0; i < 2; i++)
        #pragma unroll
        for (int j = 0; j < 8; j++)
            #pragma unroll
            for (int r = 0; r < 4; r++) c_[i][j][r] = 0.f;

    for (int ks = 0; ks < K / 16; ks++) {
        int k2b = ks * 8;
        uint32_t ah[2][4], alr[2][4];
        #pragma unroll
        for (int i = 0; i < 2; i++) {
            int r = wm * 32 + i * 16 + g;
            ah[i][0]  = sAh[r * ASp + k2b + q];
            ah[i][1]  = sAh[(r + 8) * ASp + k2b + q];
            ah[i][2]  = sAh[r * ASp + k2b + 4 + q];
            ah[i][3]  = sAh[(r + 8) * ASp + k2b + 4 + q];
            alr[i][0] = sAl[r * ASp + k2b + q];
            alr[i][1] = sAl[(r + 8) * ASp + k2b + q];
            alr[i][2] = sAl[r * ASp + k2b + 4 + q];
            alr[i][3] = sAl[(r + 8) * ASp + k2b + 4 + q];
        }
        #pragma unroll
        for (int j = 0; j < 8; j++) {
            int ncol = wn * 64 + j * 8 + g;
            uint32_t bh0 = sWh[(k2b + q) * WSp + ncol];
            uint32_t bh1 = sWh[(k2b + 4 + q) * WSp + ncol];
            uint32_t bl0 = sWl[(k2b + q) * WSp + ncol];
            uint32_t bl1 = sWl[(k2b + 4 + q) * WSp + ncol];
            #pragma unroll
            for (int i = 0; i < 2; i++) {
                mma_bf16(c_[i][j], ah[i], bh0, bh1);
                mma_bf16(c_[i][j], ah[i], bl0, bl1);
                mma_bf16(c_[i][j], alr[i], bh0, bh1);
            }
        }
    }

    // Epilogue: store feat (fp16), fused el/er (this warp's head = wn, fp32)
    float alv[8][2], arv[8][2];
    #pragma unroll
    for (int j = 0; j < 8; j++) {
        int col = wn * 64 + j * 8 + 2 * q;
        alv[j][0] = al[col]; alv[j][1] = al[col + 1];
        arv[j][0] = ar[col]; arv[j][1] = ar[col + 1];
    }
    #pragma unroll
    for (int i = 0; i < 2; i++) {
        int rtop = n0 + wm * 32 + i * 16 + g;
        int rbot = rtop + 8;
        float plt = 0.f, prt = 0.f, plb = 0.f, prb = 0.f;
        #pragma unroll
        for (int j = 0; j < 8; j++) {
            int cb = wn * 64 + j * 8 + 2 * q;
            if (rtop < NN)
                *(__half2*)&g_feat_h[(size_t)rtop * HD + cb] =
                    __floats2half2_rn(c_[i][j][0], c_[i][j][1]);
            if (rbot < NN)
                *(__half2*)&g_feat_h[(size_t)rbot * HD + cb] =
                    __floats2half2_rn(c_[i][j][2], c_[i][j][3]);
            plt += c_[i][j][0] * alv[j][0] + c_[i][j][1] * alv[j][1];
            prt += c_[i][j][0] * arv[j][0] + c_[i][j][1] * arv[j][1];
            plb += c_[i][j][2] * alv[j][0] + c_[i][j][3] * alv[j][1];
            prb += c_[i][j][2] * arv[j][0] + c_[i][j][3] * arv[j][1];
        }
        #pragma unroll
        for (int o = 1; o <= 2; o <<= 1) {
            plt += __shfl_xor_sync(0xffffffffu, plt, o);
            prt += __shfl_xor_sync(0xffffffffu, prt, o);
            plb += __shfl_xor_sync(0xffffffffu, plb, o);
            prb += __shfl_xor_sync(0xffffffffu, prb, o);
        }
        if (q == 0) {
            if (rtop < NN) { g_el[rtop * HH + wn] = plt; g_er[rtop * HH + wn] = prt; }
            if (rbot < NN) { g_el[rbot * HH + wn] = plb; g_er[rbot * HH + wn] = prb; }
        }
    }
}

// ---------------------------------------------------------------------------
// Warp-per-node edge softmax + aggregation (R8 form — best measured).
// ---------------------------------------------------------------------------
__device__ __forceinline__ float lrelu(float e) {
    return e > 0.f ? e : NEG_SLOPE * e;
}

template <bool MEAN>
__global__ void __launch_bounds__(256) edge_agg_w(
    const float* __restrict__ b, float* __restrict__ out)
{
    __shared__ float s_w_all[8][HH][33];
    __shared__ int   s_src_all[8][32];

    int t = threadIdx.x, lane = t & 31, wid = t >> 5;
    int n = blockIdx.x * 8 + wid;
    if (n >= NN) return;

    float (*s_w)[33] = s_w_all[wid];
    int* s_src = s_src_all[wid];

    int rb  = g_rowptr[n];
    int deg = g_rowptr[n + 1] - rb;

    int h = lane >> 3;
    float acc[8];
    #pragma unroll
    for (int i = 0; i < 8; i++) acc[i] = 0.f;

    const uint4* fb = (const uint4*)g_feat_h;

    if (deg > 0 && deg <= 32) {
        float4 er4 = *(const float4*)(g_er + n * HH);
        float e0 = -1e30f, e1 = -1e30f, e2 = -1e30f, e3 = -1e30f;
        if (lane < deg) {
            int sn = g_csr[rb + lane];
            s_src[lane] = sn;
            float4 el4 = *(const float4*)(g_el + sn * HH);
            e0 = lrelu(el4.x + er4.x);
            e1 = lrelu(el4.y + er4.y);
            e2 = lrelu(el4.z + er4.z);
            e3 = lrelu(el4.w + er4.w);
        }
        float m0 = e0, m1 = e1, m2 = e2, m3 = e3;
        #pragma unroll
        for (int o = 16; o; o >>= 1) {
            m0 = fmaxf(m0, __shfl_xor_sync(0xffffffffu, m0, o));
            m1 = fmaxf(m1, __shfl_xor_sync(0xffffffffu, m1, o));
            m2 = fmaxf(m2, __shfl_xor_sync(0xffffffffu, m2, o));
            m3 = fmaxf(m3, __shfl_xor_sync(0xffffffffu, m3, o));
        }
        float w0 = 0.f, w1 = 0.f, w2 = 0.f, w3 = 0.f;
        if (lane < deg) {
            w0 = __expf(e0 - m0);
            w1 = __expf(e1 - m1);
            w2 = __expf(e2 - m2);
            w3 = __expf(e3 - m3);
        }
        float s0 = w0, s1 = w1, s2 = w2, s3 = w3;
        #pragma unroll
        for (int o = 16; o; o >>= 1) {
            s0 += __shfl_xor_sync(0xffffffffu, s0, o);
            s1 += __shfl_xor_sync(0xffffffffu, s1, o);
            s2 += __shfl_xor_sync(0xffffffffu, s2, o);
            s3 += __shfl_xor_sync(0xffffffffu, s3, o);
        }
        if (lane < deg) {
            s_w[0][lane] = w0 / s0;
            s_w[1][lane] = w1 / s1;
            s_w[2][lane] = w2 / s2;
            s_w[3][lane] = w3 / s3;
        }
        __syncwarp();

        for (int j = 0; j < deg; j++) {
            int   sn = s_src[j];
            float w  = s_w[h][j];
            uint4 f  = fb[(size_t)sn * 32 + lane];
            float2 p0 = __half22float2(*(const __half2*)&f.x);
            float2 p1 = __half22float2(*(const __half2*)&f.y);
            float2 p2 = __half22float2(*(const __half2*)&f.z);
            float2 p3 = __half22float2(*(const __half2*)&f.w);
            acc[0] += w * p0.x; acc[1] += w * p0.y;
            acc[2] += w * p1.x; acc[3] += w * p1.y;
            acc[4] += w * p2.x; acc[5] += w * p2.y;
            acc[6] += w * p3.x; acc[7] += w * p3.y;
        }
    } else if (deg > 32) {
        float er_h = g_er[n * HH + h];
        float m = -1e30f;
        for (int j = 0; j < deg; j++) {
            int sn = g_csr[rb + j];
            m = fmaxf(m, lrelu(g_el[sn * HH + h] + er_h));
        }
        float s = 0.f;
        for (int j = 0; j < deg; j++) {
            int sn = g_csr[rb + j];
            s += __expf(lrelu(g_el[sn * HH + h] + er_h) - m);
        }
        float inv = 1.0f / s;
        for (int j = 0; j < deg; j++) {
            int sn = g_csr[rb + j];
            float w = __expf(lrelu(g_el[sn * HH + h] + er_h) - m) * inv;
            uint4 f = fb[(size_t)sn * 32 + lane];
            float2 p0 = __half22float2(*(const __half2*)&f.x);
            float2 p1 = __half22float2(*(const __half2*)&f.y);
            float2 p2 = __half22float2(*(const __half2*)&f.z);
            float2 p3 = __half22float2(*(const __half2*)&f.w);
            acc[0] += w * p0.x; acc[1] += w * p0.y;
            acc[2] += w * p1.x; acc[3] += w * p1.y;
            acc[4] += w * p2.x; acc[5] += w * p2.y;
            acc[6] += w * p3.x; acc[7] += w * p3.y;
        }
    }

    if (MEAN) {
        #pragma unroll
        for (int o = 8; o <= 16; o <<= 1)
            #pragma unroll
            for (int i = 0; i < 8; i++)
                acc[i] += __shfl_down_sync(0xffffffffu, acc[i], o);
        if (lane < 8) {
            int d0 = lane * 8;
            float r[8];
            #pragma unroll
            for (int i = 0; i < 8; i++) {
                int d = d0 + i;
                r[i] = 0.25f * (acc[i] + b[d] + b[DD + d] + b[2 * DD + d] + b[3 * DD + d]);
            }
            float4* o4 = (float4*)(out + (size_t)n * DD + d0);
            o4[0] = make_float4(r[0], r[1], r[2], r[3]);
            o4[1] = make_float4(r[4], r[5], r[6], r[7]);
        }
    } else {
        int d0 = lane * 8;
        float r[8];
        #pragma unroll
        for (int i = 0; i < 8; i++) r[i] = acc[i] + b[d0 + i];
        float4* o4 = (float4*)(out + (size_t)n * HD + d0);
        o4[0] = make_float4(r[0], r[1], r[2], r[3]);
        o4[1] = make_float4(r[4], r[5], r[6], r[7]);
    }
}

// ---------------------------------------------------------------------------
// Final Linear(256->64) + LayerNorm (no affine). 16 nodes/block, 64 threads.
// ---------------------------------------------------------------------------
__global__ void __launch_bounds__(64) final_ln_k(
    const float* __restrict__ hin, const float* __restrict__ Wo,
    const float* __restrict__ bo, float* __restrict__ out)
{
    constexpr int NB = 16;
    constexpr int K4 = HD / 4;               // 64
    __shared__ float4 sh4[NB * K4];          // 16 KB
    __shared__ float so[NB * DD];            // 4 KB
    __shared__ float mu_s[NB], rs_s[NB];
    int t = threadIdx.x;
    int n0 = blockIdx.x * NB;

    const float4* hin4 = (const float4*)(hin + (size_t)n0 * HD);
    for (int idx = t; idx < NB * K4; idx += 64)
        sh4[idx] = hin4[idx];
    __syncthreads();

    float acc[NB];
    #pragma unroll
    for (int i = 0; i < NB; i++) acc[i] = 0.f;
    float bv = bo[t];

    for (int k4 = 0; k4 < K4; k4++) {
        int k = k4 * 4;
        float w0 = __ldg(&Wo[(k + 0) * DD + t]);
        float w1 = __ldg(&Wo[(k + 1) * DD + t]);
        float w2 = __ldg(&Wo[(k + 2) * DD + t]);
        float w3 = __ldg(&Wo[(k + 3) * DD + t]);
        #pragma unroll
        for (int i = 0; i < NB; i++) {
            float4 s = sh4[i * K4 + k4];
            acc[i] += s.x * w0;
            acc[i] += s.y * w1;
            acc[i] += s.z * w2;
            acc[i] += s.w * w3;
        }
    }

    #pragma unroll
    for (int i = 0; i < NB; i++) so[i * DD + t] = acc[i] + bv;
    __syncthreads();

    if (t < NB) {
        float s = 0.f;
        for (int j = 0; j < DD; j++) s += so[t * DD + j];
        float mu = s * (1.0f / DD);
        float s2 = 0.f;
        for (int j = 0; j < DD; j++) {
            float d = so[t * DD + j] - mu;
            s2 += d * d;
        }
        mu_s[t] = mu;
        rs_s[t] = rsqrtf(s2 * (1.0f / DD) + 1e-5f);
    }
    __syncthreads();

    #pragma unroll
    for (int i = 0; i < NB; i++)
        out[(size_t)(n0 + i) * DD + t] = (so[i * DD + t] - mu_s[i]) * rs_s[i];
}

// ---------------------------------------------------------------------------
// Launch: inputs (metadata order):
// 0 in_feat[N,128] 1 src[E] 2 dst[E] 3 W1[128,256] 4 al1[4,64] 5 ar1[4,64]
// 6 b1[256] 7 Wh[3,64,256] 8 alh[3,4,64] 9 arh[3,4,64] 10 bh[3,256]
// 11 Wo[256,64] 12 bo[64]  -> out float32 [N,64]
//
// Two-stream fork: after split_zero, the CSR chain (hist/scan/scatter) runs
// on a second non-blocking stream concurrent with the layer-1 GEMM; joined
// via event before the first edge_agg. Stream/event creation happens once
// (host-side, on the uncaptured correctness call); captured work is
// identical on every call.
// ---------------------------------------------------------------------------
extern "C" void kernel_launch(void* const* d_in, const int* in_sizes, int n_in,
                              void* d_out, int out_size)
{
    const float* in_feat = (const float*)d_in[0];
    const int*   src     = (const int*)d_in[1];
    const int*   dst     = (const int*)d_in[2];
    const float* W1      = (const float*)d_in[3];
    const float* al1     = (const float*)d_in[4];
    const float* ar1     = (const float*)d_in[5];
    const float* b1      = (const float*)d_in[6];
    const float* Whp     = (const float*)d_in[7];
    const float* alh     = (const float*)d_in[8];
    const float* arh     = (const float*)d_in[9];
    const float* bh      = (const float*)d_in[10];
    const float* Wo      = (const float*)d_in[11];
    const float* bo      = (const float*)d_in[12];
    float* out = (float*)d_out;

    float* g_h_ptr;
    cudaGetSymbolAddress((void**)&g_h_ptr, g_h);

    static cudaStream_t s2 = nullptr;
    static cudaEvent_t ev_fork = nullptr, ev_join = nullptr;
    if (s2 == nullptr) {
        cudaStreamCreateWithFlags(&s2, cudaStreamNonBlocking);
        cudaEventCreateWithFlags(&ev_fork, cudaEventDisableTiming);
        cudaEventCreateWithFlags(&ev_join, cudaEventDisableTiming);
    }

    // smem: 2*64*ASp + 2*K2*WSp uint32
    const int SMEM1 = (2 * 64 * (IN_F / 2 + 4) + 2 * (IN_F / 2) * 264) * 4; // 169984
    const int SMEMH = (2 * 64 * (DD / 2 + 4) + 2 * (DD / 2) * 264) * 4;     //  86016
    cudaFuncSetAttribute(gemm_mma_k<IN_F>,
                         cudaFuncAttributeMaxDynamicSharedMemorySize, SMEM1);
    cudaFuncSetAttribute(gemm_mma_k<DD>,
                         cudaFuncAttributeMaxDynamicSharedMemorySize, SMEMH);

    const int GMMA = (NN + 63) / 64;   // 782 blocks
    const int GAGG = (NN + 7) / 8;     // 6250 blocks (8 nodes/block)

    // layer W offsets (uint32 units, k-pair packed)
    const int WF0 = 0, WF1 = 16384, WF2 = 16384 + 8192, WF3 = 16384 + 2 * 8192;

    // Weight split (all layers) + g_cur zeroing, one launch (main stream).
    split_zero_k<<<(40960 + NN + 255) / 256, 256>>>(W1, Whp);
    cudaEventRecord(ev_fork, 0);

    // CSR chain on stream s2 (depends only on g_cur zeroing)
    cudaStreamWaitEvent(s2, ev_fork, 0);
    hist_k<<<(EE + 255) / 256, 256, 0, s2>>>(dst);
    scan1_k<<<SCAN_BLOCKS, 1024, 0, s2>>>();
    scan2_k<<<SCAN_BLOCKS, 1024, 0, s2>>>();
    scatter_k<<<(EE + 255) / 256, 256, 0, s2>>>(src, dst);
    cudaEventRecord(ev_join, s2);

    // Layer-1 GEMM on main stream, concurrent with CSR chain
    gemm_mma_k<IN_F><<<GMMA, 256, SMEM1>>>(in_feat, WF0, al1, ar1);

    // Join: edge_agg needs both CSR and feat
    cudaStreamWaitEvent(0, ev_join, 0);
    edge_agg_w<true><<<GAGG, 256>>>(b1, g_h_ptr);

    // Hidden layers 0,1 (mean)
    gemm_mma_k<DD><<<GMMA, 256, SMEMH>>>(g_h_ptr, WF1, alh + 0 * HD, arh + 0 * HD);
    edge_agg_w<true><<<GAGG, 256>>>(bh + 0 * HD, g_h_ptr);
    gemm_mma_k<DD><<<GMMA, 256, SMEMH>>>(g_h_ptr, WF2, alh + 1 * HD, arh + 1 * HD);
    edge_agg_w<true><<<GAGG, 256>>>(bh + 1 * HD, g_h_ptr);

    // Hidden layer 2 (full [N,H,D] output)
    gemm_mma_k<DD><<<GMMA, 256, SMEMH>>>(g_h_ptr, WF3, alh + 2 * HD, arh + 2 * HD);
    edge_agg_w<false><<<GAGG, 256>>>(bh + 2 * HD, g_h_ptr);

    // Final linear + LayerNorm -> d_out
    final_ln_k<<<NN / 16, 64>>>(g_h_ptr, Wo, bo, out);
}

// round 13
// speedup vs baseline: 1.0470x; 1.0088x over previous
#include <cuda_runtime.h>
#include <cuda_bf16.h>
#include <cuda_fp16.h>
#include <cstdint>

// Problem constants (match reference_code)
#define NN 50000      // nodes
#define EE 800000     // edges
#define IN_F 128
#define DD 64
#define HH 4
#define HD 256        // H*D
#define NEG_SLOPE 0.2f

#define SCAN_CHUNK 4096
#define SCAN_BLOCKS ((NN + SCAN_CHUNK - 1) / SCAN_CHUNK)   // 13

// ---------------------------------------------------------------------------
// Scratch (static __device__ arrays — no allocation allowed)
// ---------------------------------------------------------------------------
__device__ __half   g_feat_h[(size_t)NN * HD]; // projected features [N,256] fp16
__device__ float    g_h[(size_t)NN * HD];      // last-layer io buffer (fp32)
__device__ uint32_t g_Ah[(size_t)NN * 32];     // hidden activations bf16-hi (k-pairs)
__device__ uint32_t g_Al[(size_t)NN * 32];     // hidden activations bf16-lo
__device__ float    g_el[(size_t)NN * HH];
__device__ float    g_er[(size_t)NN * HH];
__device__ int      g_rowptr[NN + 1];
__device__ int      g_cur[NN];
__device__ int      g_csr[EE];                 // src per CSR slot (sorted by dst)
__device__ int      g_bsum[SCAN_BLOCKS];       // scan phase-1 block totals
// W bf16 hi/lo, k-pairs packed, ALL layers: L0 64*256, L1-3 each 32*256
__device__ uint32_t g_Wph[16384 + 3 * 8192];
__device__ uint32_t g_Wpl[16384 + 3 * 8192];

// ---------------------------------------------------------------------------
// CSR build: (zero fused into split) -> histogram -> scan1 -> scan2 -> scatter
// ---------------------------------------------------------------------------
__global__ void hist_k(const int* __restrict__ dst) {
    int e = blockIdx.x * blockDim.x + threadIdx.x;
    if (e < EE) atomicAdd(&g_cur[dst[e]], 1);
}

__global__ void __launch_bounds__(1024) scan1_k() {
    __shared__ int ws[32];
    int t = threadIdx.x, lane = t & 31, wid = t >> 5;
    int i0 = blockIdx.x * SCAN_CHUNK + t * 4;
    int4 v = make_int4(0, 0, 0, 0);
    if (i0 < NN) {
        v = *(const int4*)&g_cur[i0];
        *(int4*)&g_cur[i0] = make_int4(0, 0, 0, 0);
    }
    int tsum = v.x + v.y + v.z + v.w;
    int x = tsum;
    #pragma unroll
    for (int o = 1; o < 32; o <<= 1) {
        int y = __shfl_up_sync(0xffffffffu, x, o);
        if (lane >= o) x += y;
    }
    if (lane == 31) ws[wid] = x;
    __syncthreads();
    if (wid == 0) {
        int y = ws[lane];
        #pragma unroll
        for (int o = 1; o < 32; o <<= 1) {
            int z = __shfl_up_sync(0xffffffffu, y, o);
            if (lane >= o) y += z;
        }
        ws[lane] = y;
    }
    __syncthreads();
    int excl = x - tsum + (wid ? ws[wid - 1] : 0);
    if (i0 < NN) {
        g_rowptr[i0]     = excl;
        g_rowptr[i0 + 1] = excl + v.x;
        g_rowptr[i0 + 2] = excl + v.x + v.y;
        g_rowptr[i0 + 3] = excl + v.x + v.y + v.z;
    }
    if (t == 1023) g_bsum[blockIdx.x] = ws[31];
}

__global__ void __launch_bounds__(1024) scan2_k() {
    __shared__ int s_off, s_tot;
    int t = threadIdx.x, b = blockIdx.x;
    if (t == 0) {
        int off = 0, tot = 0;
        #pragma unroll
        for (int j = 0; j < SCAN_BLOCKS; j++) {
            int v = g_bsum[j];
            if (j < b) off += v;
            tot += v;
        }
        s_off = off; s_tot = tot;
    }
    __syncthreads();
    int off = s_off;
    int i0 = b * SCAN_CHUNK + t * 4;
    if (off != 0 && i0 < NN) {
        int4 r = *(int4*)&g_rowptr[i0];
        r.x += off; r.y += off; r.z += off; r.w += off;
        *(int4*)&g_rowptr[i0] = r;
    }
    if (b == 0 && t == 0) g_rowptr[NN] = s_tot;
}

__global__ void scatter_k(const int* __restrict__ src, const int* __restrict__ dst) {
    int e = blockIdx.x * blockDim.x + threadIdx.x;
    if (e < EE) {
        int d = dst[e];
        int pos = g_rowptr[d] + atomicAdd(&g_cur[d], 1);
        g_csr[pos] = src[e];
    }
}

// ---------------------------------------------------------------------------
// bf16 split helpers
// ---------------------------------------------------------------------------
__device__ __forceinline__ void bf16_split(float v, __nv_bfloat16& h, __nv_bfloat16& l) {
    h = __float2bfloat16_rn(v);
    l = __float2bfloat16_rn(v - __bfloat162float(h));
}
__device__ __forceinline__ uint32_t pack_bf16(__nv_bfloat16 lo, __nv_bfloat16 hi) {
    __nv_bfloat162 p = __halves2bfloat162(lo, hi);
    return *reinterpret_cast<uint32_t*>(&p);
}
__device__ __forceinline__ uint32_t split_pack_pair(float v0, float v1,
                                                    uint32_t& lo_out) {
    __nv_bfloat16 h0, l0, h1, l1;
    bf16_split(v0, h0, l0);
    bf16_split(v1, h1, l1);
    lo_out = pack_bf16(l0, l1);
    return pack_bf16(h0, h1);
}

// Split ALL layer weights (k-pair packed hi/lo), one launch, AND zero g_cur.
__global__ void split_zero_k(const float* __restrict__ W1,
                             const float* __restrict__ Whp)
{
    int tid = blockIdx.x * blockDim.x + threadIdx.x;
    if (tid >= 40960) {
        int z = tid - 40960;
        if (z < NN) g_cur[z] = 0;
        return;
    }
    const float* W;
    int local, off;
    if (tid < 16384) {                      // layer 0, K2=64
        W = W1; local = tid; off = 0;
    } else {
        int t2 = tid - 16384;
        int layer = t2 >> 13;               // 0..2
        W = Whp + (size_t)layer * DD * HD;
        local = t2 & 8191;
        off = 16384 + layer * 8192;
    }
    int k2 = local >> 8, n = local & 255;
    uint32_t lo;
    uint32_t hi = split_pack_pair(W[(2 * k2) * 256 + n],
                                  W[(2 * k2 + 1) * 256 + n], lo);
    g_Wph[off + local] = hi;
    g_Wpl[off + local] = lo;
}

// ---------------------------------------------------------------------------
// bf16 3-term tensor-core GEMM + fused attention coefficients (R10 mainloop).
// D = Ah*Wh + Ah*Wl + Al*Wh.
// Block: 256 thr = 8 warps, 2(M) x 4(N); warp tile m32 x n64 (1 head/warp).
// PRESPLIT=false: A read from fp32 hin and split in-kernel (layer 1, K=128).
// PRESPLIT=true : A read from g_Ah/g_Al (hidden layers, K=64) — pure copy.
// ---------------------------------------------------------------------------
__device__ __forceinline__ void mma_bf16(float* c, const uint32_t* a,
                                         uint32_t b0, uint32_t b1)
{
    asm volatile(
        "mma.sync.aligned.m16n8k16.row.col.f32.bf16.bf16.f32 "
        "{%0,%1,%2,%3}, {%4,%5,%6,%7}, {%8,%9}, {%0,%1,%2,%3};"
        : "+f"(c[0]), "+f"(c[1]), "+f"(c[2]), "+f"(c[3])
        : "r"(a[0]), "r"(a[1]), "r"(a[2]), "r"(a[3]), "r"(b0), "r"(b1));
}

template <int K, bool PRESPLIT>
__global__ void __launch_bounds__(256) gemm_mma_k(
    const float* __restrict__ hin, int w_off,
    const float* __restrict__ al, const float* __restrict__ ar)
{
    constexpr int K2  = K / 2;
    constexpr int ASp = K2 + 4;   // ≡ 4 (mod 32): A frag loads conflict-free
    constexpr int WSp = 264;      // ≡ 8 (mod 32): B frag loads conflict-free
    extern __shared__ uint32_t smu[];
    uint32_t* sAh = smu;                         // 64*ASp
    uint32_t* sAl = sAh + 64 * ASp;              // 64*ASp
    uint32_t* sWh = sAl + 64 * ASp;              // K2*WSp
    uint32_t* sWl = sWh + K2 * WSp;              // K2*WSp

    int t = threadIdx.x, lane = t & 31, wid = t >> 5;
    int wm = wid >> 2, wn = wid & 3;     // warp M-row, warp N-col (= head)
    int g = lane >> 2, q = lane & 3;     // groupID (row), quad lane
    int n0 = blockIdx.x * 64;

    if (PRESPLIT) {
        // A pre-split by previous agg: straight uint4 copies (K2 == 32)
        for (int idx = t; idx < 64 * 8; idx += 256) {
            int r = idx >> 3, c4 = (idx & 7) * 4;
            uint4 h = make_uint4(0, 0, 0, 0), l = make_uint4(0, 0, 0, 0);
            if (n0 + r < NN) {
                h = *(const uint4*)&g_Ah[(size_t)(n0 + r) * 32 + c4];
                l = *(const uint4*)&g_Al[(size_t)(n0 + r) * 32 + c4];
            }
            *(uint4*)&sAh[r * ASp + c4] = h;   // ASp=36: 16B-aligned
            *(uint4*)&sAl[r * ASp + c4] = l;
        }
    } else {
        for (int idx = t; idx < 64 * K2; idx += 256) {
            int r = idx / K2, k2 = idx % K2;
            float v0 = 0.f, v1 = 0.f;
            if (n0 + r < NN) {
                float2 vv = *(const float2*)&hin[(size_t)(n0 + r) * K + 2 * k2];
                v0 = vv.x; v1 = vv.y;
            }
            uint32_t lo;
            uint32_t hi = split_pack_pair(v0, v1, lo);
            sAh[r * ASp + k2] = hi;
            sAl[r * ASp + k2] = lo;
        }
    }
    // Stage full W (hi/lo)
    for (int idx = t; idx < K2 * 256; idx += 256) {
        int k2 = idx >> 8, n = idx & 255;
        sWh[k2 * WSp + n] = g_Wph[w_off + idx];
        sWl[k2 * WSp + n] = g_Wpl[w_off + idx];
    }
    __syncthreads();

    float c_[2][8][4];
    #pragma unroll
    for (int i = 0; i < 2; i++)
        #pragma unroll
        for (int j = 0; j < 8; j++)
            #pragma unroll
            for (int r = 0; r < 4; r++) c_[i][j][r] = 0.f;

    for (int ks = 0; ks < K / 16; ks++) {
        int k2b = ks * 8;
        uint32_t ah[2][4], alr[2][4];
        #pragma unroll
        for (int i = 0; i < 2; i++) {
            int r = wm * 32 + i * 16 + g;
            ah[i][0]  = sAh[r * ASp + k2b + q];
            ah[i][1]  = sAh[(r + 8) * ASp + k2b + q];
            ah[i][2]  = sAh[r * ASp + k2b + 4 + q];
            ah[i][3]  = sAh[(r + 8) * ASp + k2b + 4 + q];
            alr[i][0] = sAl[r * ASp + k2b + q];
            alr[i][1] = sAl[(r + 8) * ASp + k2b + q];
            alr[i][2] = sAl[r * ASp + k2b + 4 + q];
            alr[i][3] = sAl[(r + 8) * ASp + k2b + 4 + q];
        }
        #pragma unroll
        for (int j = 0; j < 8; j++) {
            int ncol = wn * 64 + j * 8 + g;
            uint32_t bh0 = sWh[(k2b + q) * WSp + ncol];
            uint32_t bh1 = sWh[(k2b + 4 + q) * WSp + ncol];
            uint32_t bl0 = sWl[(k2b + q) * WSp + ncol];
            uint32_t bl1 = sWl[(k2b + 4 + q) * WSp + ncol];
            #pragma unroll
            for (int i = 0; i < 2; i++) {
                mma_bf16(c_[i][j], ah[i], bh0, bh1);
                mma_bf16(c_[i][j], ah[i], bl0, bl1);
                mma_bf16(c_[i][j], alr[i], bh0, bh1);
            }
        }
    }

    // Epilogue: store feat (fp16), fused el/er (this warp's head = wn, fp32)
    float alv[8][2], arv[8][2];
    #pragma unroll
    for (int j = 0; j < 8; j++) {
        int col = wn * 64 + j * 8 + 2 * q;
        alv[j][0] = al[col]; alv[j][1] = al[col + 1];
        arv[j][0] = ar[col]; arv[j][1] = ar[col + 1];
    }
    #pragma unroll
    for (int i = 0; i < 2; i++) {
        int rtop = n0 + wm * 32 + i * 16 + g;
        int rbot = rtop + 8;
        float plt = 0.f, prt = 0.f, plb = 0.f, prb = 0.f;
        #pragma unroll
        for (int j = 0; j < 8; j++) {
            int cb = wn * 64 + j * 8 + 2 * q;
            if (rtop < NN)
                *(__half2*)&g_feat_h[(size_t)rtop * HD + cb] =
                    __floats2half2_rn(c_[i][j][0], c_[i][j][1]);
            if (rbot < NN)
                *(__half2*)&g_feat_h[(size_t)rbot * HD + cb] =
                    __floats2half2_rn(c_[i][j][2], c_[i][j][3]);
            plt += c_[i][j][0] * alv[j][0] + c_[i][j][1] * alv[j][1];
            prt += c_[i][j][0] * arv[j][0] + c_[i][j][1] * arv[j][1];
            plb += c_[i][j][2] * alv[j][0] + c_[i][j][3] * alv[j][1];
            prb += c_[i][j][2] * arv[j][0] + c_[i][j][3] * arv[j][1];
        }
        #pragma unroll
        for (int o = 1; o <= 2; o <<= 1) {
            plt += __shfl_xor_sync(0xffffffffu, plt, o);
            prt += __shfl_xor_sync(0xffffffffu, prt, o);
            plb += __shfl_xor_sync(0xffffffffu, plb, o);
            prb += __shfl_xor_sync(0xffffffffu, prb, o);
        }
        if (q == 0) {
            if (rtop < NN) { g_el[rtop * HH + wn] = plt; g_er[rtop * HH + wn] = prt; }
            if (rbot < NN) { g_el[rbot * HH + wn] = plb; g_er[rbot * HH + wn] = prb; }
        }
    }
}

// ---------------------------------------------------------------------------
// Warp-per-node edge softmax + aggregation.
// MEAN=true : head-mean + bias, write pre-split bf16 hi/lo to g_Ah/g_Al
//             (consumed directly by the next GEMM's A staging).
// MEAN=false: write full [N,256] fp32 + bias to out (consumed by final_ln).
// Gather loop unrolled x2 (two independent LDG.128 chains per warp).
// ---------------------------------------------------------------------------
__device__ __forceinline__ float lrelu(float e) {
    return e > 0.f ? e : NEG_SLOPE * e;
}

template <bool MEAN>
__global__ void __launch_bounds__(256) edge_agg_w(
    const float* __restrict__ b, float* __restrict__ out)
{
    __shared__ float s_w_all[8][HH][33];
    __shared__ int   s_src_all[8][32];

    int t = threadIdx.x, lane = t & 31, wid = t >> 5;
    int n = blockIdx.x * 8 + wid;
    if (n >= NN) return;

    float (*s_w)[33] = s_w_all[wid];
    int* s_src = s_src_all[wid];

    int rb  = g_rowptr[n];
    int deg = g_rowptr[n + 1] - rb;

    int h = lane >> 3;
    float acc[8];
    #pragma unroll
    for (int i = 0; i < 8; i++) acc[i] = 0.f;

    const uint4* fb = (const uint4*)g_feat_h;

    if (deg > 0 && deg <= 32) {
        float4 er4 = *(const float4*)(g_er + n * HH);
        float e0 = -1e30f, e1 = -1e30f, e2 = -1e30f, e3 = -1e30f;
        if (lane < deg) {
            int sn = g_csr[rb + lane];
            s_src[lane] = sn;
            float4 el4 = *(const float4*)(g_el + sn * HH);
            e0 = lrelu(el4.x + er4.x);
            e1 = lrelu(el4.y + er4.y);
            e2 = lrelu(el4.z + er4.z);
            e3 = lrelu(el4.w + er4.w);
        }
        float m0 = e0, m1 = e1, m2 = e2, m3 = e3;
        #pragma unroll
        for (int o = 16; o; o >>= 1) {
            m0 = fmaxf(m0, __shfl_xor_sync(0xffffffffu, m0, o));
            m1 = fmaxf(m1, __shfl_xor_sync(0xffffffffu, m1, o));
            m2 = fmaxf(m2, __shfl_xor_sync(0xffffffffu, m2, o));
            m3 = fmaxf(m3, __shfl_xor_sync(0xffffffffu, m3, o));
        }
        float w0 = 0.f, w1 = 0.f, w2 = 0.f, w3 = 0.f;
        if (lane < deg) {
            w0 = __expf(e0 - m0);
            w1 = __expf(e1 - m1);
            w2 = __expf(e2 - m2);
            w3 = __expf(e3 - m3);
        }
        float s0 = w0, s1 = w1, s2 = w2, s3 = w3;
        #pragma unroll
        for (int o = 16; o; o >>= 1) {
            s0 += __shfl_xor_sync(0xffffffffu, s0, o);
            s1 += __shfl_xor_sync(0xffffffffu, s1, o);
            s2 += __shfl_xor_sync(0xffffffffu, s2, o);
            s3 += __shfl_xor_sync(0xffffffffu, s3, o);
        }
        if (lane < deg) {
            s_w[0][lane] = w0 / s0;
            s_w[1][lane] = w1 / s1;
            s_w[2][lane] = w2 / s2;
            s_w[3][lane] = w3 / s3;
        }
        __syncwarp();

        int j = 0;
        for (; j + 2 <= deg; j += 2) {
            int   sn0 = s_src[j],    sn1 = s_src[j + 1];
            float w0_ = s_w[h][j],   w1_ = s_w[h][j + 1];
            uint4 f0 = fb[(size_t)sn0 * 32 + lane];
            uint4 f1 = fb[(size_t)sn1 * 32 + lane];
            float2 a0 = __half22float2(*(const __half2*)&f0.x);
            float2 a1 = __half22float2(*(const __half2*)&f0.y);
            float2 a2 = __half22float2(*(const __half2*)&f0.z);
            float2 a3 = __half22float2(*(const __half2*)&f0.w);
            float2 b0 = __half22float2(*(const __half2*)&f1.x);
            float2 b1 = __half22float2(*(const __half2*)&f1.y);
            float2 b2 = __half22float2(*(const __half2*)&f1.z);
            float2 b3 = __half22float2(*(const __half2*)&f1.w);
            acc[0] += w0_ * a0.x + w1_ * b0.x;
            acc[1] += w0_ * a0.y + w1_ * b0.y;
            acc[2] += w0_ * a1.x + w1_ * b1.x;
            acc[3] += w0_ * a1.y + w1_ * b1.y;
            acc[4] += w0_ * a2.x + w1_ * b2.x;
            acc[5] += w0_ * a2.y + w1_ * b2.y;
            acc[6] += w0_ * a3.x + w1_ * b3.x;
            acc[7] += w0_ * a3.y + w1_ * b3.y;
        }
        if (j < deg) {
            int   sn = s_src[j];
            float w  = s_w[h][j];
            uint4 f  = fb[(size_t)sn * 32 + lane];
            float2 p0 = __half22float2(*(const __half2*)&f.x);
            float2 p1 = __half22float2(*(const __half2*)&f.y);
            float2 p2 = __half22float2(*(const __half2*)&f.z);
            float2 p3 = __half22float2(*(const __half2*)&f.w);
            acc[0] += w * p0.x; acc[1] += w * p0.y;
            acc[2] += w * p1.x; acc[3] += w * p1.y;
            acc[4] += w * p2.x; acc[5] += w * p2.y;
            acc[6] += w * p3.x; acc[7] += w * p3.y;
        }
    } else if (deg > 32) {
        float er_h = g_er[n * HH + h];
        float m = -1e30f;
        for (int j = 0; j < deg; j++) {
            int sn = g_csr[rb + j];
            m = fmaxf(m, lrelu(g_el[sn * HH + h] + er_h));
        }
        float s = 0.f;
        for (int j = 0; j < deg; j++) {
            int sn = g_csr[rb + j];
            s += __expf(lrelu(g_el[sn * HH + h] + er_h) - m);
        }
        float inv = 1.0f / s;
        for (int j = 0; j < deg; j++) {
            int sn = g_csr[rb + j];
            float w = __expf(lrelu(g_el[sn * HH + h] + er_h) - m) * inv;
            uint4 f = fb[(size_t)sn * 32 + lane];
            float2 p0 = __half22float2(*(const __half2*)&f.x);
            float2 p1 = __half22float2(*(const __half2*)&f.y);
            float2 p2 = __half22float2(*(const __half2*)&f.z);
            float2 p3 = __half22float2(*(const __half2*)&f.w);
            acc[0] += w * p0.x; acc[1] += w * p0.y;
            acc[2] += w * p1.x; acc[3] += w * p1.y;
            acc[4] += w * p2.x; acc[5] += w * p2.y;
            acc[6] += w * p3.x; acc[7] += w * p3.y;
        }
    }

    if (MEAN) {
        #pragma unroll
        for (int o = 8; o <= 16; o <<= 1)
            #pragma unroll
            for (int i = 0; i < 8; i++)
                acc[i] += __shfl_down_sync(0xffffffffu, acc[i], o);
        if (lane < 8) {
            int d0 = lane * 8;
            float r[8];
            #pragma unroll
            for (int i = 0; i < 8; i++) {
                int d = d0 + i;
                r[i] = 0.25f * (acc[i] + b[d] + b[DD + d] + b[2 * DD + d] + b[3 * DD + d]);
            }
            // pre-split to bf16 hi/lo k-pairs for the next GEMM's A staging
            uint32_t hi[4], lo[4];
            #pragma unroll
            for (int p = 0; p < 4; p++)
                hi[p] = split_pack_pair(r[2 * p], r[2 * p + 1], lo[p]);
            *(uint4*)&g_Ah[(size_t)n * 32 + lane * 4] =
                make_uint4(hi[0], hi[1], hi[2], hi[3]);
            *(uint4*)&g_Al[(size_t)n * 32 + lane * 4] =
                make_uint4(lo[0], lo[1], lo[2], lo[3]);
        }
    } else {
        int d0 = lane * 8;
        float r[8];
        #pragma unroll
        for (int i = 0; i < 8; i++) r[i] = acc[i] + b[d0 + i];
        float4* o4 = (float4*)(out + (size_t)n * HD + d0);
        o4[0] = make_float4(r[0], r[1], r[2], r[3]);
        o4[1] = make_float4(r[4], r[5], r[6], r[7]);
    }
}

// ---------------------------------------------------------------------------
// Final Linear(256->64) + LayerNorm (no affine). 16 nodes/block, 64 threads.
// ---------------------------------------------------------------------------
__global__ void __launch_bounds__(64) final_ln_k(
    const float* __restrict__ hin, const float* __restrict__ Wo,
    const float* __restrict__ bo, float* __restrict__ out)
{
    constexpr int NB = 16;
    constexpr int K4 = HD / 4;               // 64
    __shared__ float4 sh4[NB * K4];          // 16 KB
    __shared__ float so[NB * DD];            // 4 KB
    __shared__ float mu_s[NB], rs_s[NB];
    int t = threadIdx.x;
    int n0 = blockIdx.x * NB;

    const float4* hin4 = (const float4*)(hin + (size_t)n0 * HD);
    for (int idx = t; idx < NB * K4; idx += 64)
        sh4[idx] = hin4[idx];
    __syncthreads();

    float acc[NB];
    #pragma unroll
    for (int i = 0; i < NB; i++) acc[i] = 0.f;
    float bv = bo[t];

    for (int k4 = 0; k4 < K4; k4++) {
        int k = k4 * 4;
        float w0 = __ldg(&Wo[(k + 0) * DD + t]);
        float w1 = __ldg(&Wo[(k + 1) * DD + t]);
        float w2 = __ldg(&Wo[(k + 2) * DD + t]);
        float w3 = __ldg(&Wo[(k + 3) * DD + t]);
        #pragma unroll
        for (int i = 0; i < NB; i++) {
            float4 s = sh4[i * K4 + k4];
            acc[i] += s.x * w0;
            acc[i] += s.y * w1;
            acc[i] += s.z * w2;
            acc[i] += s.w * w3;
        }
    }

    #pragma unroll
    for (int i = 0; i < NB; i++) so[i * DD + t] = acc[i] + bv;
    __syncthreads();

    if (t < NB) {
        float s = 0.f;
        for (int j = 0; j < DD; j++) s += so[t * DD + j];
        float mu = s * (1.0f / DD);
        float s2 = 0.f;
        for (int j = 0; j < DD; j++) {
            float d = so[t * DD + j] - mu;
            s2 += d * d;
        }
        mu_s[t] = mu;
        rs_s[t] = rsqrtf(s2 * (1.0f / DD) + 1e-5f);
    }
    __syncthreads();

    #pragma unroll
    for (int i = 0; i < NB; i++)
        out[(size_t)(n0 + i) * DD + t] = (so[i * DD + t] - mu_s[i]) * rs_s[i];
}

// ---------------------------------------------------------------------------
// Launch (two-stream fork for CSR vs layer-1 GEMM, as in R12).
// ---------------------------------------------------------------------------
extern "C" void kernel_launch(void* const* d_in, const int* in_sizes, int n_in,
                              void* d_out, int out_size)
{
    const float* in_feat = (const float*)d_in[0];
    const int*   src     = (const int*)d_in[1];
    const int*   dst     = (const int*)d_in[2];
    const float* W1      = (const float*)d_in[3];
    const float* al1     = (const float*)d_in[4];
    const float* ar1     = (const float*)d_in[5];
    const float* b1      = (const float*)d_in[6];
    const float* Whp     = (const float*)d_in[7];
    const float* alh     = (const float*)d_in[8];
    const float* arh     = (const float*)d_in[9];
    const float* bh      = (const float*)d_in[10];
    const float* Wo      = (const float*)d_in[11];
    const float* bo      = (const float*)d_in[12];
    float* out = (float*)d_out;

    float* g_h_ptr;
    cudaGetSymbolAddress((void**)&g_h_ptr, g_h);

    static cudaStream_t s2 = nullptr;
    static cudaEvent_t ev_fork = nullptr, ev_join = nullptr;
    if (s2 == nullptr) {
        cudaStreamCreateWithFlags(&s2, cudaStreamNonBlocking);
        cudaEventCreateWithFlags(&ev_fork, cudaEventDisableTiming);
        cudaEventCreateWithFlags(&ev_join, cudaEventDisableTiming);
    }

    // smem: 2*64*ASp + 2*K2*WSp uint32
    const int SMEM1 = (2 * 64 * (IN_F / 2 + 4) + 2 * (IN_F / 2) * 264) * 4; // 169984
    const int SMEMH = (2 * 64 * (DD / 2 + 4) + 2 * (DD / 2) * 264) * 4;     //  86016
    cudaFuncSetAttribute((const void*)gemm_mma_k<IN_F, false>,
                         cudaFuncAttributeMaxDynamicSharedMemorySize, SMEM1);
    cudaFuncSetAttribute((const void*)gemm_mma_k<DD, true>,
                         cudaFuncAttributeMaxDynamicSharedMemorySize, SMEMH);

    const int GMMA = (NN + 63) / 64;   // 782 blocks
    const int GAGG = (NN + 7) / 8;     // 6250 blocks (8 nodes/block)

    // layer W offsets (uint32 units, k-pair packed)
    const int WF0 = 0, WF1 = 16384, WF2 = 16384 + 8192, WF3 = 16384 + 2 * 8192;

    // Weight split (all layers) + g_cur zeroing, one launch (main stream).
    split_zero_k<<<(40960 + NN + 255) / 256, 256>>>(W1, Whp);
    cudaEventRecord(ev_fork, 0);

    // CSR chain on stream s2 (depends only on g_cur zeroing)
    cudaStreamWaitEvent(s2, ev_fork, 0);
    hist_k<<<(EE + 255) / 256, 256, 0, s2>>>(dst);
    scan1_k<<<SCAN_BLOCKS, 1024, 0, s2>>>();
    scan2_k<<<SCAN_BLOCKS, 1024, 0, s2>>>();
    scatter_k<<<(EE + 255) / 256, 256, 0, s2>>>(src, dst);
    cudaEventRecord(ev_join, s2);

    // Layer-1 GEMM on main stream, concurrent with CSR chain
    gemm_mma_k<IN_F, false><<<GMMA, 256, SMEM1>>>(in_feat, WF0, al1, ar1);

    // Join: edge_agg needs both CSR and feat
    cudaStreamWaitEvent(0, ev_join, 0);
    edge_agg_w<true><<<GAGG, 256>>>(b1, nullptr);

    // Hidden layers 0,1 (mean) — A pre-split by previous agg
    gemm_mma_k<DD, true><<<GMMA, 256, SMEMH>>>(nullptr, WF1, alh + 0 * HD, arh + 0 * HD);
    edge_agg_w<true><<<GAGG, 256>>>(bh + 0 * HD, nullptr);
    gemm_mma_k<DD, true><<<GMMA, 256, SMEMH>>>(nullptr, WF2, alh + 1 * HD, arh + 1 * HD);
    edge_agg_w<true><<<GAGG, 256>>>(bh + 1 * HD, nullptr);

    // Hidden layer 2 (full [N,H,D] output)
    gemm_mma_k<DD, true><<<GMMA, 256, SMEMH>>>(nullptr, WF3, alh + 2 * HD, arh + 2 * HD);
    edge_agg_w<false><<<GAGG, 256>>>(bh + 2 * HD, g_h_ptr);

    // Final linear + LayerNorm -> d_out
    final_ln_k<<<NN / 16, 64>>>(g_h_ptr, Wo, bo, out);
}

// round 14
// speedup vs baseline: 1.1392x; 1.0881x over previous
#include <cuda_runtime.h>
#include <cuda_bf16.h>
#include <cuda_fp16.h>
#include <cstdint>

// Problem constants (match reference_code)
#define NN 50000      // nodes
#define EE 800000     // edges
#define IN_F 128
#define DD 64
#define HH 4
#define HD 256        // H*D
#define NEG_SLOPE 0.2f

#define SCAN_CHUNK 4096
#define SCAN_BLOCKS ((NN + SCAN_CHUNK - 1) / SCAN_CHUNK)   // 13
#define NTILES ((NN + 63) / 64)                            // 782

// ---------------------------------------------------------------------------
// Scratch (static __device__ arrays — no allocation allowed)
// ---------------------------------------------------------------------------
__device__ __half   g_feat_h[(size_t)NN * HD]; // projected features [N,256] fp16
__device__ float    g_h[(size_t)NN * HD];      // last-layer io buffer (fp32)
__device__ uint32_t g_Ah[(size_t)NN * 32];     // hidden activations bf16-hi (k-pairs)
__device__ uint32_t g_Al[(size_t)NN * 32];     // hidden activations bf16-lo
__device__ float    g_el[(size_t)NN * HH];
__device__ float    g_er[(size_t)NN * HH];
__device__ int      g_rowptr[NN + 1];
__device__ int      g_cur[NN];
__device__ int      g_csr[EE];                 // src per CSR slot (sorted by dst)
__device__ int      g_bsum[SCAN_BLOCKS];       // scan phase-1 block totals
// W bf16 hi/lo, k-pairs packed, ALL layers: L0 64*256, L1-3 each 32*256
__device__ uint32_t g_Wph[16384 + 3 * 8192];
__device__ uint32_t g_Wpl[16384 + 3 * 8192];

// ---------------------------------------------------------------------------
// CSR build: (zero fused into split) -> histogram -> scan1 -> scan2 -> scatter
// ---------------------------------------------------------------------------
__global__ void hist_k(const int* __restrict__ dst) {
    int e = blockIdx.x * blockDim.x + threadIdx.x;
    if (e < EE) atomicAdd(&g_cur[dst[e]], 1);
}

__global__ void __launch_bounds__(1024) scan1_k() {
    __shared__ int ws[32];
    int t = threadIdx.x, lane = t & 31, wid = t >> 5;
    int i0 = blockIdx.x * SCAN_CHUNK + t * 4;
    int4 v = make_int4(0, 0, 0, 0);
    if (i0 < NN) {
        v = *(const int4*)&g_cur[i0];
        *(int4*)&g_cur[i0] = make_int4(0, 0, 0, 0);
    }
    int tsum = v.x + v.y + v.z + v.w;
    int x = tsum;
    #pragma unroll
    for (int o = 1; o < 32; o <<= 1) {
        int y = __shfl_up_sync(0xffffffffu, x, o);
        if (lane >= o) x += y;
    }
    if (lane == 31) ws[wid] = x;
    __syncthreads();
    if (wid == 0) {
        int y = ws[lane];
        #pragma unroll
        for (int o = 1; o < 32; o <<= 1) {
            int z = __shfl_up_sync(0xffffffffu, y, o);
            if (lane >= o) y += z;
        }
        ws[lane] = y;
    }
    __syncthreads();
    int excl = x - tsum + (wid ? ws[wid - 1] : 0);
    if (i0 < NN) {
        g_rowptr[i0]     = excl;
        g_rowptr[i0 + 1] = excl + v.x;
        g_rowptr[i0 + 2] = excl + v.x + v.y;
        g_rowptr[i0 + 3] = excl + v.x + v.y + v.z;
    }
    if (t == 1023) g_bsum[blockIdx.x] = ws[31];
}

__global__ void __launch_bounds__(1024) scan2_k() {
    __shared__ int s_off, s_tot;
    int t = threadIdx.x, b = blockIdx.x;
    if (t == 0) {
        int off = 0, tot = 0;
        #pragma unroll
        for (int j = 0; j < SCAN_BLOCKS; j++) {
            int v = g_bsum[j];
            if (j < b) off += v;
            tot += v;
        }
        s_off = off; s_tot = tot;
    }
    __syncthreads();
    int off = s_off;
    int i0 = b * SCAN_CHUNK + t * 4;
    if (off != 0 && i0 < NN) {
        int4 r = *(int4*)&g_rowptr[i0];
        r.x += off; r.y += off; r.z += off; r.w += off;
        *(int4*)&g_rowptr[i0] = r;
    }
    if (b == 0 && t == 0) g_rowptr[NN] = s_tot;
}

__global__ void scatter_k(const int* __restrict__ src, const int* __restrict__ dst) {
    int e = blockIdx.x * blockDim.x + threadIdx.x;
    if (e < EE) {
        int d = dst[e];
        int pos = g_rowptr[d] + atomicAdd(&g_cur[d], 1);
        g_csr[pos] = src[e];
    }
}

// ---------------------------------------------------------------------------
// bf16 split helpers
// ---------------------------------------------------------------------------
__device__ __forceinline__ void bf16_split(float v, __nv_bfloat16& h, __nv_bfloat16& l) {
    h = __float2bfloat16_rn(v);
    l = __float2bfloat16_rn(v - __bfloat162float(h));
}
__device__ __forceinline__ uint32_t pack_bf16(__nv_bfloat16 lo, __nv_bfloat16 hi) {
    __nv_bfloat162 p = __halves2bfloat162(lo, hi);
    return *reinterpret_cast<uint32_t*>(&p);
}
__device__ __forceinline__ uint32_t split_pack_pair(float v0, float v1,
                                                    uint32_t& lo_out) {
    __nv_bfloat16 h0, l0, h1, l1;
    bf16_split(v0, h0, l0);
    bf16_split(v1, h1, l1);
    lo_out = pack_bf16(l0, l1);
    return pack_bf16(h0, h1);
}

// Split ALL layer weights (k-pair packed hi/lo), one launch, AND zero g_cur.
__global__ void split_zero_k(const float* __restrict__ W1,
                             const float* __restrict__ Whp)
{
    int tid = blockIdx.x * blockDim.x + threadIdx.x;
    if (tid >= 40960) {
        int z = tid - 40960;
        if (z < NN) g_cur[z] = 0;
        return;
    }
    const float* W;
    int local, off;
    if (tid < 16384) {                      // layer 0, K2=64
        W = W1; local = tid; off = 0;
    } else {
        int t2 = tid - 16384;
        int layer = t2 >> 13;               // 0..2
        W = Whp + (size_t)layer * DD * HD;
        local = t2 & 8191;
        off = 16384 + layer * 8192;
    }
    int k2 = local >> 8, n = local & 255;
    uint32_t lo;
    uint32_t hi = split_pack_pair(W[(2 * k2) * 256 + n],
                                  W[(2 * k2 + 1) * 256 + n], lo);
    g_Wph[off + local] = hi;
    g_Wpl[off + local] = lo;
}

// ---------------------------------------------------------------------------
// Persistent bf16 3-term tensor-core GEMM + fused attention coefficients.
// D = Ah*Wh + Ah*Wl + Al*Wh. W staged in smem ONCE per block; each block
// loops over node tiles (stride gridDim) with double-buffered A and ONE
// __syncthreads per tile. Safety: a warp staging buffer b at tile i passed
// the barrier of tile i-1, which it reached only after computing tile i-2
// (last user of b).
// Block: 256 thr = 8 warps, 2(M) x 4(N); warp tile m32 x n64 (1 head/warp).
// ---------------------------------------------------------------------------
__device__ __forceinline__ void mma_bf16(float* c, const uint32_t* a,
                                         uint32_t b0, uint32_t b1)
{
    asm volatile(
        "mma.sync.aligned.m16n8k16.row.col.f32.bf16.bf16.f32 "
        "{%0,%1,%2,%3}, {%4,%5,%6,%7}, {%8,%9}, {%0,%1,%2,%3};"
        : "+f"(c[0]), "+f"(c[1]), "+f"(c[2]), "+f"(c[3])
        : "r"(a[0]), "r"(a[1]), "r"(a[2]), "r"(a[3]), "r"(b0), "r"(b1));
}

template <int K, bool PRESPLIT>
__global__ void __launch_bounds__(256) gemm_mma_k(
    const float* __restrict__ hin, int w_off,
    const float* __restrict__ al, const float* __restrict__ ar)
{
    constexpr int K2  = K / 2;
    constexpr int ASp = K2 + 4;   // ≡ 4 (mod 32): A frag loads conflict-free
    constexpr int WSp = 264;      // ≡ 8 (mod 32): B frag loads conflict-free
    constexpr int ABUF = 64 * ASp;
    extern __shared__ uint32_t smu[];
    uint32_t* sAh = smu;                         // 2 bufs x 64*ASp
    uint32_t* sAl = sAh + 2 * ABUF;              // 2 bufs x 64*ASp
    uint32_t* sWh = sAl + 2 * ABUF;              // K2*WSp
    uint32_t* sWl = sWh + K2 * WSp;              // K2*WSp

    int t = threadIdx.x, lane = t & 31, wid = t >> 5;
    int wm = wid >> 2, wn = wid & 3;     // warp M-row, warp N-col (= head)
    int g = lane >> 2, q = lane & 3;     // groupID (row), quad lane
    int gdim = gridDim.x;

    // Stage full W once (hi/lo)
    for (int idx = t; idx < K2 * 256; idx += 256) {
        int k2 = idx >> 8, n = idx & 255;
        sWh[k2 * WSp + n] = g_Wph[w_off + idx];
        sWl[k2 * WSp + n] = g_Wpl[w_off + idx];
    }

    // Epilogue coefficients (tile-invariant)
    float alv[8][2], arv[8][2];
    #pragma unroll
    for (int j = 0; j < 8; j++) {
        int col = wn * 64 + j * 8 + 2 * q;
        alv[j][0] = al[col]; alv[j][1] = al[col + 1];
        arv[j][0] = ar[col]; arv[j][1] = ar[col + 1];
    }

    int buf = 0;
    for (int tile = blockIdx.x; tile < NTILES; tile += gdim, buf ^= 1) {
        int n0 = tile * 64;
        uint32_t* bAh = sAh + buf * ABUF;
        uint32_t* bAl = sAl + buf * ABUF;

        // Stage A into current buffer
        if (PRESPLIT) {
            for (int idx = t; idx < 64 * 8; idx += 256) {
                int r = idx >> 3, c4 = (idx & 7) * 4;
                uint4 h = make_uint4(0, 0, 0, 0), l = make_uint4(0, 0, 0, 0);
                if (n0 + r < NN) {
                    h = *(const uint4*)&g_Ah[(size_t)(n0 + r) * 32 + c4];
                    l = *(const uint4*)&g_Al[(size_t)(n0 + r) * 32 + c4];
                }
                *(uint4*)&bAh[r * ASp + c4] = h;
                *(uint4*)&bAl[r * ASp + c4] = l;
            }
        } else {
            for (int idx = t; idx < 64 * K2; idx += 256) {
                int r = idx / K2, k2 = idx % K2;
                float v0 = 0.f, v1 = 0.f;
                if (n0 + r < NN) {
                    float2 vv = *(const float2*)&hin[(size_t)(n0 + r) * K + 2 * k2];
                    v0 = vv.x; v1 = vv.y;
                }
                uint32_t lo;
                uint32_t hi = split_pack_pair(v0, v1, lo);
                bAh[r * ASp + k2] = hi;
                bAl[r * ASp + k2] = lo;
            }
        }
        __syncthreads();

        float c_[2][8][4];
        #pragma unroll
        for (int i = 0; i < 2; i++)
            #pragma unroll
            for (int j = 0; j < 8; j++)
                #pragma unroll
                for (int r = 0; r < 4; r++) c_[i][j][r] = 0.f;

        for (int ks = 0; ks < K / 16; ks++) {
            int k2b = ks * 8;
            uint32_t ah[2][4], alr[2][4];
            #pragma unroll
            for (int i = 0; i < 2; i++) {
                int r = wm * 32 + i * 16 + g;
                ah[i][0]  = bAh[r * ASp + k2b + q];
                ah[i][1]  = bAh[(r + 8) * ASp + k2b + q];
                ah[i][2]  = bAh[r * ASp + k2b + 4 + q];
                ah[i][3]  = bAh[(r + 8) * ASp + k2b + 4 + q];
                alr[i][0] = bAl[r * ASp + k2b + q];
                alr[i][1] = bAl[(r + 8) * ASp + k2b + q];
                alr[i][2] = bAl[r * ASp + k2b + 4 + q];
                alr[i][3] = bAl[(r + 8) * ASp + k2b + 4 + q];
            }
            #pragma unroll
            for (int j = 0; j < 8; j++) {
                int ncol = wn * 64 + j * 8 + g;
                uint32_t bh0 = sWh[(k2b + q) * WSp + ncol];
                uint32_t bh1 = sWh[(k2b + 4 + q) * WSp + ncol];
                uint32_t bl0 = sWl[(k2b + q) * WSp + ncol];
                uint32_t bl1 = sWl[(k2b + 4 + q) * WSp + ncol];
                #pragma unroll
                for (int i = 0; i < 2; i++) {
                    mma_bf16(c_[i][j], ah[i], bh0, bh1);
                    mma_bf16(c_[i][j], ah[i], bl0, bl1);
                    mma_bf16(c_[i][j], alr[i], bh0, bh1);
                }
            }
        }

        // Epilogue: store feat (fp16), fused el/er
        #pragma unroll
        for (int i = 0; i < 2; i++) {
            int rtop = n0 + wm * 32 + i * 16 + g;
            int rbot = rtop + 8;
            float plt = 0.f, prt = 0.f, plb = 0.f, prb = 0.f;
            #pragma unroll
            for (int j = 0; j < 8; j++) {
                int cb = wn * 64 + j * 8 + 2 * q;
                if (rtop < NN)
                    *(__half2*)&g_feat_h[(size_t)rtop * HD + cb] =
                        __floats2half2_rn(c_[i][j][0], c_[i][j][1]);
                if (rbot < NN)
                    *(__half2*)&g_feat_h[(size_t)rbot * HD + cb] =
                        __floats2half2_rn(c_[i][j][2], c_[i][j][3]);
                plt += c_[i][j][0] * alv[j][0] + c_[i][j][1] * alv[j][1];
                prt += c_[i][j][0] * arv[j][0] + c_[i][j][1] * arv[j][1];
                plb += c_[i][j][2] * alv[j][0] + c_[i][j][3] * alv[j][1];
                prb += c_[i][j][2] * arv[j][0] + c_[i][j][3] * arv[j][1];
            }
            #pragma unroll
            for (int o = 1; o <= 2; o <<= 1) {
                plt += __shfl_xor_sync(0xffffffffu, plt, o);
                prt += __shfl_xor_sync(0xffffffffu, prt, o);
                plb += __shfl_xor_sync(0xffffffffu, plb, o);
                prb += __shfl_xor_sync(0xffffffffu, prb, o);
            }
            if (q == 0) {
                if (rtop < NN) { g_el[rtop * HH + wn] = plt; g_er[rtop * HH + wn] = prt; }
                if (rbot < NN) { g_el[rbot * HH + wn] = plb; g_er[rbot * HH + wn] = prb; }
            }
        }
    }
}

// ---------------------------------------------------------------------------
// Warp-per-node edge softmax + aggregation.
// MEAN=true : head-mean + bias -> pre-split bf16 hi/lo to g_Ah/g_Al.
// MEAN=false: full [N,256] fp32 + bias to out. Gather unrolled x2.
// ---------------------------------------------------------------------------
__device__ __forceinline__ float lrelu(float e) {
    return e > 0.f ? e : NEG_SLOPE * e;
}

template <bool MEAN>
__global__ void __launch_bounds__(256) edge_agg_w(
    const float* __restrict__ b, float* __restrict__ out)
{
    __shared__ float s_w_all[8][HH][33];
    __shared__ int   s_src_all[8][32];

    int t = threadIdx.x, lane = t & 31, wid = t >> 5;
    int n = blockIdx.x * 8 + wid;
    if (n >= NN) return;

    float (*s_w)[33] = s_w_all[wid];
    int* s_src = s_src_all[wid];

    int rb  = g_rowptr[n];
    int deg = g_rowptr[n + 1] - rb;

    int h = lane >> 3;
    float acc[8];
    #pragma unroll
    for (int i = 0; i < 8; i++) acc[i] = 0.f;

    const uint4* fb = (const uint4*)g_feat_h;

    if (deg > 0 && deg <= 32) {
        float4 er4 = *(const float4*)(g_er + n * HH);
        float e0 = -1e30f, e1 = -1e30f, e2 = -1e30f, e3 = -1e30f;
        if (lane < deg) {
            int sn = g_csr[rb + lane];
            s_src[lane] = sn;
            float4 el4 = *(const float4*)(g_el + sn * HH);
            e0 = lrelu(el4.x + er4.x);
            e1 = lrelu(el4.y + er4.y);
            e2 = lrelu(el4.z + er4.z);
            e3 = lrelu(el4.w + er4.w);
        }
        float m0 = e0, m1 = e1, m2 = e2, m3 = e3;
        #pragma unroll
        for (int o = 16; o; o >>= 1) {
            m0 = fmaxf(m0, __shfl_xor_sync(0xffffffffu, m0, o));
            m1 = fmaxf(m1, __shfl_xor_sync(0xffffffffu, m1, o));
            m2 = fmaxf(m2, __shfl_xor_sync(0xffffffffu, m2, o));
            m3 = fmaxf(m3, __shfl_xor_sync(0xffffffffu, m3, o));
        }
        float w0 = 0.f, w1 = 0.f, w2 = 0.f, w3 = 0.f;
        if (lane < deg) {
            w0 = __expf(e0 - m0);
            w1 = __expf(e1 - m1);
            w2 = __expf(e2 - m2);
            w3 = __expf(e3 - m3);
        }
        float s0 = w0, s1 = w1, s2 = w2, s3 = w3;
        #pragma unroll
        for (int o = 16; o; o >>= 1) {
            s0 += __shfl_xor_sync(0xffffffffu, s0, o);
            s1 += __shfl_xor_sync(0xffffffffu, s1, o);
            s2 += __shfl_xor_sync(0xffffffffu, s2, o);
            s3 += __shfl_xor_sync(0xffffffffu, s3, o);
        }
        if (lane < deg) {
            s_w[0][lane] = w0 / s0;
            s_w[1][lane] = w1 / s1;
            s_w[2][lane] = w2 / s2;
            s_w[3][lane] = w3 / s3;
        }
        __syncwarp();

        int j = 0;
        for (; j + 2 <= deg; j += 2) {
            int   sn0 = s_src[j],    sn1 = s_src[j + 1];
            float w0_ = s_w[h][j],   w1_ = s_w[h][j + 1];
            uint4 f0 = fb[(size_t)sn0 * 32 + lane];
            uint4 f1 = fb[(size_t)sn1 * 32 + lane];
            float2 a0 = __half22float2(*(const __half2*)&f0.x);
            float2 a1 = __half22float2(*(const __half2*)&f0.y);
            float2 a2 = __half22float2(*(const __half2*)&f0.z);
            float2 a3 = __half22float2(*(const __half2*)&f0.w);
            float2 b0 = __half22float2(*(const __half2*)&f1.x);
            float2 b1 = __half22float2(*(const __half2*)&f1.y);
            float2 b2 = __half22float2(*(const __half2*)&f1.z);
            float2 b3 = __half22float2(*(const __half2*)&f1.w);
            acc[0] += w0_ * a0.x + w1_ * b0.x;
            acc[1] += w0_ * a0.y + w1_ * b0.y;
            acc[2] += w0_ * a1.x + w1_ * b1.x;
            acc[3] += w0_ * a1.y + w1_ * b1.y;
            acc[4] += w0_ * a2.x + w1_ * b2.x;
            acc[5] += w0_ * a2.y + w1_ * b2.y;
            acc[6] += w0_ * a3.x + w1_ * b3.x;
            acc[7] += w0_ * a3.y + w1_ * b3.y;
        }
        if (j < deg) {
            int   sn = s_src[j];
            float w  = s_w[h][j];
            uint4 f  = fb[(size_t)sn * 32 + lane];
            float2 p0 = __half22float2(*(const __half2*)&f.x);
            float2 p1 = __half22float2(*(const __half2*)&f.y);
            float2 p2 = __half22float2(*(const __half2*)&f.z);
            float2 p3 = __half22float2(*(const __half2*)&f.w);
            acc[0] += w * p0.x; acc[1] += w * p0.y;
            acc[2] += w * p1.x; acc[3] += w * p1.y;
            acc[4] += w * p2.x; acc[5] += w * p2.y;
            acc[6] += w * p3.x; acc[7] += w * p3.y;
        }
    } else if (deg > 32) {
        float er_h = g_er[n * HH + h];
        float m = -1e30f;
        for (int j = 0; j < deg; j++) {
            int sn = g_csr[rb + j];
            m = fmaxf(m, lrelu(g_el[sn * HH + h] + er_h));
        }
        float s = 0.f;
        for (int j = 0; j < deg; j++) {
            int sn = g_csr[rb + j];
            s += __expf(lrelu(g_el[sn * HH + h] + er_h) - m);
        }
        float inv = 1.0f / s;
        for (int j = 0; j < deg; j++) {
            int sn = g_csr[rb + j];
            float w = __expf(lrelu(g_el[sn * HH + h] + er_h) - m) * inv;
            uint4 f = fb[(size_t)sn * 32 + lane];
            float2 p0 = __half22float2(*(const __half2*)&f.x);
            float2 p1 = __half22float2(*(const __half2*)&f.y);
            float2 p2 = __half22float2(*(const __half2*)&f.z);
            float2 p3 = __half22float2(*(const __half2*)&f.w);
            acc[0] += w * p0.x; acc[1] += w * p0.y;
            acc[2] += w * p1.x; acc[3] += w * p1.y;
            acc[4] += w * p2.x; acc[5] += w * p2.y;
            acc[6] += w * p3.x; acc[7] += w * p3.y;
        }
    }

    if (MEAN) {
        #pragma unroll
        for (int o = 8; o <= 16; o <<= 1)
            #pragma unroll
            for (int i = 0; i < 8; i++)
                acc[i] += __shfl_down_sync(0xffffffffu, acc[i], o);
        if (lane < 8) {
            int d0 = lane * 8;
            float r[8];
            #pragma unroll
            for (int i = 0; i < 8; i++) {
                int d = d0 + i;
                r[i] = 0.25f * (acc[i] + b[d] + b[DD + d] + b[2 * DD + d] + b[3 * DD + d]);
            }
            uint32_t hi[4], lo[4];
            #pragma unroll
            for (int p = 0; p < 4; p++)
                hi[p] = split_pack_pair(r[2 * p], r[2 * p + 1], lo[p]);
            *(uint4*)&g_Ah[(size_t)n * 32 + lane * 4] =
                make_uint4(hi[0], hi[1], hi[2], hi[3]);
            *(uint4*)&g_Al[(size_t)n * 32 + lane * 4] =
                make_uint4(lo[0], lo[1], lo[2], lo[3]);
        }
    } else {
        int d0 = lane * 8;
        float r[8];
        #pragma unroll
        for (int i = 0; i < 8; i++) r[i] = acc[i] + b[d0 + i];
        float4* o4 = (float4*)(out + (size_t)n * HD + d0);
        o4[0] = make_float4(r[0], r[1], r[2], r[3]);
        o4[1] = make_float4(r[4], r[5], r[6], r[7]);
    }
}

// ---------------------------------------------------------------------------
// Final Linear(256->64) + LayerNorm (no affine). 16 nodes/block, 64 threads.
// ---------------------------------------------------------------------------
__global__ void __launch_bounds__(64) final_ln_k(
    const float* __restrict__ hin, const float* __restrict__ Wo,
    const float* __restrict__ bo, float* __restrict__ out)
{
    constexpr int NB = 16;
    constexpr int K4 = HD / 4;               // 64
    __shared__ float4 sh4[NB * K4];          // 16 KB
    __shared__ float so[NB * DD];            // 4 KB
    __shared__ float mu_s[NB], rs_s[NB];
    int t = threadIdx.x;
    int n0 = blockIdx.x * NB;

    const float4* hin4 = (const float4*)(hin + (size_t)n0 * HD);
    for (int idx = t; idx < NB * K4; idx += 64)
        sh4[idx] = hin4[idx];
    __syncthreads();

    float acc[NB];
    #pragma unroll
    for (int i = 0; i < NB; i++) acc[i] = 0.f;
    float bv = bo[t];

    for (int k4 = 0; k4 < K4; k4++) {
        int k = k4 * 4;
        float w0 = __ldg(&Wo[(k + 0) * DD + t]);
        float w1 = __ldg(&Wo[(k + 1) * DD + t]);
        float w2 = __ldg(&Wo[(k + 2) * DD + t]);
        float w3 = __ldg(&Wo[(k + 3) * DD + t]);
        #pragma unroll
        for (int i = 0; i < NB; i++) {
            float4 s = sh4[i * K4 + k4];
            acc[i] += s.x * w0;
            acc[i] += s.y * w1;
            acc[i] += s.z * w2;
            acc[i] += s.w * w3;
        }
    }

    #pragma unroll
    for (int i = 0; i < NB; i++) so[i * DD + t] = acc[i] + bv;
    __syncthreads();

    if (t < NB) {
        float s = 0.f;
        for (int j = 0; j < DD; j++) s += so[t * DD + j];
        float mu = s * (1.0f / DD);
        float s2 = 0.f;
        for (int j = 0; j < DD; j++) {
            float d = so[t * DD + j] - mu;
            s2 += d * d;
        }
        mu_s[t] = mu;
        rs_s[t] = rsqrtf(s2 * (1.0f / DD) + 1e-5f);
    }
    __syncthreads();

    #pragma unroll
    for (int i = 0; i < NB; i++)
        out[(size_t)(n0 + i) * DD + t] = (so[i * DD + t] - mu_s[i]) * rs_s[i];
}

// ---------------------------------------------------------------------------
// Launch (two-stream fork for CSR vs layer-1 GEMM; persistent GEMM grids).
// ---------------------------------------------------------------------------
extern "C" void kernel_launch(void* const* d_in, const int* in_sizes, int n_in,
                              void* d_out, int out_size)
{
    const float* in_feat = (const float*)d_in[0];
    const int*   src     = (const int*)d_in[1];
    const int*   dst     = (const int*)d_in[2];
    const float* W1      = (const float*)d_in[3];
    const float* al1     = (const float*)d_in[4];
    const float* ar1     = (const float*)d_in[5];
    const float* b1      = (const float*)d_in[6];
    const float* Whp     = (const float*)d_in[7];
    const float* alh     = (const float*)d_in[8];
    const float* arh     = (const float*)d_in[9];
    const float* bh      = (const float*)d_in[10];
    const float* Wo      = (const float*)d_in[11];
    const float* bo      = (const float*)d_in[12];
    float* out = (float*)d_out;

    float* g_h_ptr;
    cudaGetSymbolAddress((void**)&g_h_ptr, g_h);

    static cudaStream_t s2 = nullptr;
    static cudaEvent_t ev_fork = nullptr, ev_join = nullptr;
    if (s2 == nullptr) {
        cudaStreamCreateWithFlags(&s2, cudaStreamNonBlocking);
        cudaEventCreateWithFlags(&ev_fork, cudaEventDisableTiming);
        cudaEventCreateWithFlags(&ev_join, cudaEventDisableTiming);
    }

    // smem bytes: (4*64*ASp + 2*K2*WSp) * 4   (A double-buffered hi+lo)
    const int SMEM1 = (4 * 64 * (IN_F / 2 + 4) + 2 * (IN_F / 2) * 264) * 4; // 204800
    const int SMEMH = (4 * 64 * (DD / 2 + 4) + 2 * (DD / 2) * 264) * 4;     // 104448
    cudaFuncSetAttribute((const void*)gemm_mma_k<IN_F, false>,
                         cudaFuncAttributeMaxDynamicSharedMemorySize, SMEM1);
    cudaFuncSetAttribute((const void*)gemm_mma_k<DD, true>,
                         cudaFuncAttributeMaxDynamicSharedMemorySize, SMEMH);

    const int G1 = 148;                // persistent, 1 block/SM (200 KB smem)
    const int GH = 296;                // persistent, 2 blocks/SM (104 KB smem)
    const int GAGG = (NN + 7) / 8;     // 6250 blocks (8 nodes/block)

    // layer W offsets (uint32 units, k-pair packed)
    const int WF0 = 0, WF1 = 16384, WF2 = 16384 + 8192, WF3 = 16384 + 2 * 8192;

    // Weight split (all layers) + g_cur zeroing, one launch (main stream).
    split_zero_k<<<(40960 + NN + 255) / 256, 256>>>(W1, Whp);
    cudaEventRecord(ev_fork, 0);

    // CSR chain on stream s2 (depends only on g_cur zeroing)
    cudaStreamWaitEvent(s2, ev_fork, 0);
    hist_k<<<(EE + 255) / 256, 256, 0, s2>>>(dst);
    scan1_k<<<SCAN_BLOCKS, 1024, 0, s2>>>();
    scan2_k<<<SCAN_BLOCKS, 1024, 0, s2>>>();
    scatter_k<<<(EE + 255) / 256, 256, 0, s2>>>(src, dst);
    cudaEventRecord(ev_join, s2);

    // Layer-1 GEMM on main stream, concurrent with CSR chain
    gemm_mma_k<IN_F, false><<<G1, 256, SMEM1>>>(in_feat, WF0, al1, ar1);

    // Join: edge_agg needs both CSR and feat
    cudaStreamWaitEvent(0, ev_join, 0);
    edge_agg_w<true><<<GAGG, 256>>>(b1, nullptr);

    // Hidden layers 0,1 (mean) — A pre-split by previous agg
    gemm_mma_k<DD, true><<<GH, 256, SMEMH>>>(nullptr, WF1, alh + 0 * HD, arh + 0 * HD);
    edge_agg_w<true><<<GAGG, 256>>>(bh + 0 * HD, nullptr);
    gemm_mma_k<DD, true><<<GH, 256, SMEMH>>>(nullptr, WF2, alh + 1 * HD, arh + 1 * HD);
    edge_agg_w<true><<<GAGG, 256>>>(bh + 1 * HD, nullptr);

    // Hidden layer 2 (full [N,H,D] output)
    gemm_mma_k<DD, true><<<GH, 256, SMEMH>>>(nullptr, WF3, alh + 2 * HD, arh + 2 * HD);
    edge_agg_w<false><<<GAGG, 256>>>(bh + 2 * HD, g_h_ptr);

    // Final linear + LayerNorm -> d_out
    final_ln_k<<<NN / 16, 64>>>(g_h_ptr, Wo, bo, out);
}

// round 15
// speedup vs baseline: 1.1688x; 1.0260x over previous
#include <cuda_runtime.h>
#include <cuda_bf16.h>
#include <cuda_fp16.h>
#include <cstdint>

// Problem constants (match reference_code)
#define NN 50000      // nodes
#define EE 800000     // edges
#define IN_F 128
#define DD 64
#define HH 4
#define HD 256        // H*D
#define NEG_SLOPE 0.2f

#define SCAN_CHUNK 4096
#define SCAN_BLOCKS ((NN + SCAN_CHUNK - 1) / SCAN_CHUNK)   // 13
#define NTILES ((NN + 63) / 64)                            // 782

// ---------------------------------------------------------------------------
// Scratch (static __device__ arrays — no allocation allowed)
// ---------------------------------------------------------------------------
__device__ __half   g_feat_h[(size_t)NN * HD]; // projected features [N,256] fp16
__device__ __half   g_h16[(size_t)NN * HD];    // last-layer io buffer (fp16)
__device__ uint32_t g_Ah[(size_t)NN * 32];     // hidden activations bf16-hi (k-pairs)
__device__ uint32_t g_Al[(size_t)NN * 32];     // hidden activations bf16-lo
__device__ float    g_el[(size_t)NN * HH];
__device__ float    g_er[(size_t)NN * HH];
__device__ int      g_rowptr[NN + 1];
__device__ int      g_cur[NN];
__device__ int      g_csr[EE];                 // src per CSR slot (sorted by dst)
__device__ int      g_bsum[SCAN_BLOCKS];       // scan phase-1 block totals
// W bf16 hi/lo, k-pairs packed, ALL layers: L0 64*256, L1-3 each 32*256
__device__ uint32_t g_Wph[16384 + 3 * 8192];
__device__ uint32_t g_Wpl[16384 + 3 * 8192];

// ---------------------------------------------------------------------------
// CSR build: (zero fused into split) -> histogram -> scan1 -> scan2 -> scatter
// ---------------------------------------------------------------------------
__global__ void hist_k(const int* __restrict__ dst) {
    int e = blockIdx.x * blockDim.x + threadIdx.x;
    if (e < EE) atomicAdd(&g_cur[dst[e]], 1);
}

__global__ void __launch_bounds__(1024) scan1_k() {
    __shared__ int ws[32];
    int t = threadIdx.x, lane = t & 31, wid = t >> 5;
    int i0 = blockIdx.x * SCAN_CHUNK + t * 4;
    int4 v = make_int4(0, 0, 0, 0);
    if (i0 < NN) {
        v = *(const int4*)&g_cur[i0];
        *(int4*)&g_cur[i0] = make_int4(0, 0, 0, 0);
    }
    int tsum = v.x + v.y + v.z + v.w;
    int x = tsum;
    #pragma unroll
    for (int o = 1; o < 32; o <<= 1) {
        int y = __shfl_up_sync(0xffffffffu, x, o);
        if (lane >= o) x += y;
    }
    if (lane == 31) ws[wid] = x;
    __syncthreads();
    if (wid == 0) {
        int y = ws[lane];
        #pragma unroll
        for (int o = 1; o < 32; o <<= 1) {
            int z = __shfl_up_sync(0xffffffffu, y, o);
            if (lane >= o) y += z;
        }
        ws[lane] = y;
    }
    __syncthreads();
    int excl = x - tsum + (wid ? ws[wid - 1] : 0);
    if (i0 < NN) {
        g_rowptr[i0]     = excl;
        g_rowptr[i0 + 1] = excl + v.x;
        g_rowptr[i0 + 2] = excl + v.x + v.y;
        g_rowptr[i0 + 3] = excl + v.x + v.y + v.z;
    }
    if (t == 1023) g_bsum[blockIdx.x] = ws[31];
}

__global__ void __launch_bounds__(1024) scan2_k() {
    __shared__ int s_off, s_tot;
    int t = threadIdx.x, b = blockIdx.x;
    if (t == 0) {
        int off = 0, tot = 0;
        #pragma unroll
        for (int j = 0; j < SCAN_BLOCKS; j++) {
            int v = g_bsum[j];
            if (j < b) off += v;
            tot += v;
        }
        s_off = off; s_tot = tot;
    }
    __syncthreads();
    int off = s_off;
    int i0 = b * SCAN_CHUNK + t * 4;
    if (off != 0 && i0 < NN) {
        int4 r = *(int4*)&g_rowptr[i0];
        r.x += off; r.y += off; r.z += off; r.w += off;
        *(int4*)&g_rowptr[i0] = r;
    }
    if (b == 0 && t == 0) g_rowptr[NN] = s_tot;
}

__global__ void scatter_k(const int* __restrict__ src, const int* __restrict__ dst) {
    int e = blockIdx.x * blockDim.x + threadIdx.x;
    if (e < EE) {
        int d = dst[e];
        int pos = g_rowptr[d] + atomicAdd(&g_cur[d], 1);
        g_csr[pos] = src[e];
    }
}

// ---------------------------------------------------------------------------
// bf16 split helpers
// ---------------------------------------------------------------------------
__device__ __forceinline__ void bf16_split(float v, __nv_bfloat16& h, __nv_bfloat16& l) {
    h = __float2bfloat16_rn(v);
    l = __float2bfloat16_rn(v - __bfloat162float(h));
}
__device__ __forceinline__ uint32_t pack_bf16(__nv_bfloat16 lo, __nv_bfloat16 hi) {
    __nv_bfloat162 p = __halves2bfloat162(lo, hi);
    return *reinterpret_cast<uint32_t*>(&p);
}
__device__ __forceinline__ uint32_t split_pack_pair(float v0, float v1,
                                                    uint32_t& lo_out) {
    __nv_bfloat16 h0, l0, h1, l1;
    bf16_split(v0, h0, l0);
    bf16_split(v1, h1, l1);
    lo_out = pack_bf16(l0, l1);
    return pack_bf16(h0, h1);
}

// Split ALL layer weights (k-pair packed hi/lo), one launch, AND zero g_cur.
__global__ void split_zero_k(const float* __restrict__ W1,
                             const float* __restrict__ Whp)
{
    int tid = blockIdx.x * blockDim.x + threadIdx.x;
    if (tid >= 40960) {
        int z = tid - 40960;
        if (z < NN) g_cur[z] = 0;
        return;
    }
    const float* W;
    int local, off;
    if (tid < 16384) {                      // layer 0, K2=64
        W = W1; local = tid; off = 0;
    } else {
        int t2 = tid - 16384;
        int layer = t2 >> 13;               // 0..2
        W = Whp + (size_t)layer * DD * HD;
        local = t2 & 8191;
        off = 16384 + layer * 8192;
    }
    int k2 = local >> 8, n = local & 255;
    uint32_t lo;
    uint32_t hi = split_pack_pair(W[(2 * k2) * 256 + n],
                                  W[(2 * k2 + 1) * 256 + n], lo);
    g_Wph[off + local] = hi;
    g_Wpl[off + local] = lo;
}

// ---------------------------------------------------------------------------
// Persistent bf16 3-term tensor-core GEMM + fused attention coefficients.
// D = Ah*Wh + Ah*Wl + Al*Wh. W staged in smem ONCE per block; tiles strided
// by gridDim with double-buffered A, ONE __syncthreads per tile.
// Block: 256 thr = 8 warps, 2(M) x 4(N); warp tile m32 x n64 (1 head/warp).
// ---------------------------------------------------------------------------
__device__ __forceinline__ void mma_bf16(float* c, const uint32_t* a,
                                         uint32_t b0, uint32_t b1)
{
    asm volatile(
        "mma.sync.aligned.m16n8k16.row.col.f32.bf16.bf16.f32 "
        "{%0,%1,%2,%3}, {%4,%5,%6,%7}, {%8,%9}, {%0,%1,%2,%3};"
        : "+f"(c[0]), "+f"(c[1]), "+f"(c[2]), "+f"(c[3])
        : "r"(a[0]), "r"(a[1]), "r"(a[2]), "r"(a[3]), "r"(b0), "r"(b1));
}

template <int K, bool PRESPLIT>
__global__ void __launch_bounds__(256) gemm_mma_k(
    const float* __restrict__ hin, int w_off,
    const float* __restrict__ al, const float* __restrict__ ar)
{
    constexpr int K2  = K / 2;
    constexpr int ASp = K2 + 4;   // ≡ 4 (mod 32): A frag loads conflict-free
    constexpr int WSp = 264;      // ≡ 8 (mod 32): B frag loads conflict-free
    constexpr int ABUF = 64 * ASp;
    extern __shared__ uint32_t smu[];
    uint32_t* sAh = smu;                         // 2 bufs x 64*ASp
    uint32_t* sAl = sAh + 2 * ABUF;              // 2 bufs x 64*ASp
    uint32_t* sWh = sAl + 2 * ABUF;              // K2*WSp
    uint32_t* sWl = sWh + K2 * WSp;              // K2*WSp

    int t = threadIdx.x, lane = t & 31, wid = t >> 5;
    int wm = wid >> 2, wn = wid & 3;     // warp M-row, warp N-col (= head)
    int g = lane >> 2, q = lane & 3;     // groupID (row), quad lane
    int gdim = gridDim.x;

    // Stage full W once (hi/lo)
    for (int idx = t; idx < K2 * 256; idx += 256) {
        int k2 = idx >> 8, n = idx & 255;
        sWh[k2 * WSp + n] = g_Wph[w_off + idx];
        sWl[k2 * WSp + n] = g_Wpl[w_off + idx];
    }

    // Epilogue coefficients (tile-invariant)
    float alv[8][2], arv[8][2];
    #pragma unroll
    for (int j = 0; j < 8; j++) {
        int col = wn * 64 + j * 8 + 2 * q;
        alv[j][0] = al[col]; alv[j][1] = al[col + 1];
        arv[j][0] = ar[col]; arv[j][1] = ar[col + 1];
    }

    int buf = 0;
    for (int tile = blockIdx.x; tile < NTILES; tile += gdim, buf ^= 1) {
        int n0 = tile * 64;
        uint32_t* bAh = sAh + buf * ABUF;
        uint32_t* bAl = sAl + buf * ABUF;

        // Stage A into current buffer
        if (PRESPLIT) {
            for (int idx = t; idx < 64 * 8; idx += 256) {
                int r = idx >> 3, c4 = (idx & 7) * 4;
                uint4 h = make_uint4(0, 0, 0, 0), l = make_uint4(0, 0, 0, 0);
                if (n0 + r < NN) {
                    h = *(const uint4*)&g_Ah[(size_t)(n0 + r) * 32 + c4];
                    l = *(const uint4*)&g_Al[(size_t)(n0 + r) * 32 + c4];
                }
                *(uint4*)&bAh[r * ASp + c4] = h;
                *(uint4*)&bAl[r * ASp + c4] = l;
            }
        } else {
            for (int idx = t; idx < 64 * K2; idx += 256) {
                int r = idx / K2, k2 = idx % K2;
                float v0 = 0.f, v1 = 0.f;
                if (n0 + r < NN) {
                    float2 vv = *(const float2*)&hin[(size_t)(n0 + r) * K + 2 * k2];
                    v0 = vv.x; v1 = vv.y;
                }
                uint32_t lo;
                uint32_t hi = split_pack_pair(v0, v1, lo);
                bAh[r * ASp + k2] = hi;
                bAl[r * ASp + k2] = lo;
            }
        }
        __syncthreads();

        float c_[2][8][4];
        #pragma unroll
        for (int i = 0; i < 2; i++)
            #pragma unroll
            for (int j = 0; j < 8; j++)
                #pragma unroll
                for (int r = 0; r < 4; r++) c_[i][j][r] = 0.f;

        for (int ks = 0; ks < K / 16; ks++) {
            int k2b = ks * 8;
            uint32_t ah[2][4], alr[2][4];
            #pragma unroll
            for (int i = 0; i < 2; i++) {
                int r = wm * 32 + i * 16 + g;
                ah[i][0]  = bAh[r * ASp + k2b + q];
                ah[i][1]  = bAh[(r + 8) * ASp + k2b + q];
                ah[i][2]  = bAh[r * ASp + k2b + 4 + q];
                ah[i][3]  = bAh[(r + 8) * ASp + k2b + 4 + q];
                alr[i][0] = bAl[r * ASp + k2b + q];
                alr[i][1] = bAl[(r + 8) * ASp + k2b + q];
                alr[i][2] = bAl[r * ASp + k2b + 4 + q];
                alr[i][3] = bAl[(r + 8) * ASp + k2b + 4 + q];
            }
            #pragma unroll
            for (int j = 0; j < 8; j++) {
                int ncol = wn * 64 + j * 8 + g;
                uint32_t bh0 = sWh[(k2b + q) * WSp + ncol];
                uint32_t bh1 = sWh[(k2b + 4 + q) * WSp + ncol];
                uint32_t bl0 = sWl[(k2b + q) * WSp + ncol];
                uint32_t bl1 = sWl[(k2b + 4 + q) * WSp + ncol];
                #pragma unroll
                for (int i = 0; i < 2; i++) {
                    mma_bf16(c_[i][j], ah[i], bh0, bh1);
                    mma_bf16(c_[i][j], ah[i], bl0, bl1);
                    mma_bf16(c_[i][j], alr[i], bh0, bh1);
                }
            }
        }

        // Epilogue: store feat (fp16), fused el/er
        #pragma unroll
        for (int i = 0; i < 2; i++) {
            int rtop = n0 + wm * 32 + i * 16 + g;
            int rbot = rtop + 8;
            float plt = 0.f, prt = 0.f, plb = 0.f, prb = 0.f;
            #pragma unroll
            for (int j = 0; j < 8; j++) {
                int cb = wn * 64 + j * 8 + 2 * q;
                if (rtop < NN)
                    *(__half2*)&g_feat_h[(size_t)rtop * HD + cb] =
                        __floats2half2_rn(c_[i][j][0], c_[i][j][1]);
                if (rbot < NN)
                    *(__half2*)&g_feat_h[(size_t)rbot * HD + cb] =
                        __floats2half2_rn(c_[i][j][2], c_[i][j][3]);
                plt += c_[i][j][0] * alv[j][0] + c_[i][j][1] * alv[j][1];
                prt += c_[i][j][0] * arv[j][0] + c_[i][j][1] * arv[j][1];
                plb += c_[i][j][2] * alv[j][0] + c_[i][j][3] * alv[j][1];
                prb += c_[i][j][2] * arv[j][0] + c_[i][j][3] * arv[j][1];
            }
            #pragma unroll
            for (int o = 1; o <= 2; o <<= 1) {
                plt += __shfl_xor_sync(0xffffffffu, plt, o);
                prt += __shfl_xor_sync(0xffffffffu, prt, o);
                plb += __shfl_xor_sync(0xffffffffu, plb, o);
                prb += __shfl_xor_sync(0xffffffffu, prb, o);
            }
            if (q == 0) {
                if (rtop < NN) { g_el[rtop * HH + wn] = plt; g_er[rtop * HH + wn] = prt; }
                if (rbot < NN) { g_el[rbot * HH + wn] = plb; g_er[rbot * HH + wn] = prb; }
            }
        }
    }
}

// ---------------------------------------------------------------------------
// Warp-per-node edge softmax + aggregation.
// MEAN=true : head-mean + bias -> pre-split bf16 hi/lo to g_Ah/g_Al.
// MEAN=false: full [N,256] fp16 + bias to g_h16. Gather unrolled x4.
// ---------------------------------------------------------------------------
__device__ __forceinline__ float lrelu(float e) {
    return e > 0.f ? e : NEG_SLOPE * e;
}
__device__ __forceinline__ void acc_edge(float* acc, float w, uint4 f) {
    float2 p0 = __half22float2(*(const __half2*)&f.x);
    float2 p1 = __half22float2(*(const __half2*)&f.y);
    float2 p2 = __half22float2(*(const __half2*)&f.z);
    float2 p3 = __half22float2(*(const __half2*)&f.w);
    acc[0] += w * p0.x; acc[1] += w * p0.y;
    acc[2] += w * p1.x; acc[3] += w * p1.y;
    acc[4] += w * p2.x; acc[5] += w * p2.y;
    acc[6] += w * p3.x; acc[7] += w * p3.y;
}

template <bool MEAN>
__global__ void __launch_bounds__(256) edge_agg_w(const float* __restrict__ b)
{
    __shared__ float s_w_all[8][HH][33];
    __shared__ int   s_src_all[8][32];

    int t = threadIdx.x, lane = t & 31, wid = t >> 5;
    int n = blockIdx.x * 8 + wid;
    if (n >= NN) return;

    float (*s_w)[33] = s_w_all[wid];
    int* s_src = s_src_all[wid];

    int rb  = g_rowptr[n];
    int deg = g_rowptr[n + 1] - rb;

    int h = lane >> 3;
    float acc[8];
    #pragma unroll
    for (int i = 0; i < 8; i++) acc[i] = 0.f;

    const uint4* fb = (const uint4*)g_feat_h;

    if (deg > 0 && deg <= 32) {
        float4 er4 = *(const float4*)(g_er + n * HH);
        float e0 = -1e30f, e1 = -1e30f, e2 = -1e30f, e3 = -1e30f;
        if (lane < deg) {
            int sn = g_csr[rb + lane];
            s_src[lane] = sn;
            float4 el4 = *(const float4*)(g_el + sn * HH);
            e0 = lrelu(el4.x + er4.x);
            e1 = lrelu(el4.y + er4.y);
            e2 = lrelu(el4.z + er4.z);
            e3 = lrelu(el4.w + er4.w);
        }
        float m0 = e0, m1 = e1, m2 = e2, m3 = e3;
        #pragma unroll
        for (int o = 16; o; o >>= 1) {
            m0 = fmaxf(m0, __shfl_xor_sync(0xffffffffu, m0, o));
            m1 = fmaxf(m1, __shfl_xor_sync(0xffffffffu, m1, o));
            m2 = fmaxf(m2, __shfl_xor_sync(0xffffffffu, m2, o));
            m3 = fmaxf(m3, __shfl_xor_sync(0xffffffffu, m3, o));
        }
        float w0 = 0.f, w1 = 0.f, w2 = 0.f, w3 = 0.f;
        if (lane < deg) {
            w0 = __expf(e0 - m0);
            w1 = __expf(e1 - m1);
            w2 = __expf(e2 - m2);
            w3 = __expf(e3 - m3);
        }
        float s0 = w0, s1 = w1, s2 = w2, s3 = w3;
        #pragma unroll
        for (int o = 16; o; o >>= 1) {
            s0 += __shfl_xor_sync(0xffffffffu, s0, o);
            s1 += __shfl_xor_sync(0xffffffffu, s1, o);
            s2 += __shfl_xor_sync(0xffffffffu, s2, o);
            s3 += __shfl_xor_sync(0xffffffffu, s3, o);
        }
        if (lane < deg) {
            s_w[0][lane] = w0 / s0;
            s_w[1][lane] = w1 / s1;
            s_w[2][lane] = w2 / s2;
            s_w[3][lane] = w3 / s3;
        }
        __syncwarp();

        int j = 0;
        for (; j + 4 <= deg; j += 4) {
            int   sn0 = s_src[j],     sn1 = s_src[j + 1];
            int   sn2 = s_src[j + 2], sn3 = s_src[j + 3];
            float w0_ = s_w[h][j],     w1_ = s_w[h][j + 1];
            float w2_ = s_w[h][j + 2], w3_ = s_w[h][j + 3];
            uint4 f0 = fb[(size_t)sn0 * 32 + lane];
            uint4 f1 = fb[(size_t)sn1 * 32 + lane];
            uint4 f2 = fb[(size_t)sn2 * 32 + lane];
            uint4 f3 = fb[(size_t)sn3 * 32 + lane];
            acc_edge(acc, w0_, f0);
            acc_edge(acc, w1_, f1);
            acc_edge(acc, w2_, f2);
            acc_edge(acc, w3_, f3);
        }
        for (; j < deg; j++) {
            uint4 f = fb[(size_t)s_src[j] * 32 + lane];
            acc_edge(acc, s_w[h][j], f);
        }
    } else if (deg > 32) {
        float er_h = g_er[n * HH + h];
        float m = -1e30f;
        for (int j = 0; j < deg; j++) {
            int sn = g_csr[rb + j];
            m = fmaxf(m, lrelu(g_el[sn * HH + h] + er_h));
        }
        float s = 0.f;
        for (int j = 0; j < deg; j++) {
            int sn = g_csr[rb + j];
            s += __expf(lrelu(g_el[sn * HH + h] + er_h) - m);
        }
        float inv = 1.0f / s;
        for (int j = 0; j < deg; j++) {
            int sn = g_csr[rb + j];
            float w = __expf(lrelu(g_el[sn * HH + h] + er_h) - m) * inv;
            uint4 f = fb[(size_t)sn * 32 + lane];
            acc_edge(acc, w, f);
        }
    }

    if (MEAN) {
        #pragma unroll
        for (int o = 8; o <= 16; o <<= 1)
            #pragma unroll
            for (int i = 0; i < 8; i++)
                acc[i] += __shfl_down_sync(0xffffffffu, acc[i], o);
        if (lane < 8) {
            int d0 = lane * 8;
            float r[8];
            #pragma unroll
            for (int i = 0; i < 8; i++) {
                int d = d0 + i;
                r[i] = 0.25f * (acc[i] + b[d] + b[DD + d] + b[2 * DD + d] + b[3 * DD + d]);
            }
            uint32_t hi[4], lo[4];
            #pragma unroll
            for (int p = 0; p < 4; p++)
                hi[p] = split_pack_pair(r[2 * p], r[2 * p + 1], lo[p]);
            *(uint4*)&g_Ah[(size_t)n * 32 + lane * 4] =
                make_uint4(hi[0], hi[1], hi[2], hi[3]);
            *(uint4*)&g_Al[(size_t)n * 32 + lane * 4] =
                make_uint4(lo[0], lo[1], lo[2], lo[3]);
        }
    } else {
        int d0 = lane * 8;
        __half2 r[4];
        #pragma unroll
        for (int i = 0; i < 4; i++)
            r[i] = __floats2half2_rn(acc[2 * i] + b[d0 + 2 * i],
                                     acc[2 * i + 1] + b[d0 + 2 * i + 1]);
        *(uint2*)&g_h16[(size_t)n * HD + d0] =
            make_uint2(*(uint32_t*)&r[0], *(uint32_t*)&r[1]);
        *(uint2*)&g_h16[(size_t)n * HD + d0 + 4] =
            make_uint2(*(uint32_t*)&r[2], *(uint32_t*)&r[3]);
    }
}

// ---------------------------------------------------------------------------
// Final Linear(256->64) + LayerNorm (no affine). 16 nodes/block, 64 threads.
// Reads fp16 g_h16, stages fp32 in smem, compute unchanged.
// ---------------------------------------------------------------------------
__global__ void __launch_bounds__(64) final_ln_k(
    const float* __restrict__ Wo, const float* __restrict__ bo,
    float* __restrict__ out)
{
    constexpr int NB = 16;
    constexpr int K4 = HD / 4;               // 64
    __shared__ float4 sh4[NB * K4];          // 16 KB
    __shared__ float so[NB * DD];            // 4 KB
    __shared__ float mu_s[NB], rs_s[NB];
    int t = threadIdx.x;
    int n0 = blockIdx.x * NB;

    const uint2* hin16 = (const uint2*)(g_h16 + (size_t)n0 * HD);
    for (int idx = t; idx < NB * K4; idx += 64) {
        uint2 p = hin16[idx];
        float2 a = __half22float2(*(const __half2*)&p.x);
        float2 c = __half22float2(*(const __half2*)&p.y);
        sh4[idx] = make_float4(a.x, a.y, c.x, c.y);
    }
    __syncthreads();

    float acc[NB];
    #pragma unroll
    for (int i = 0; i < NB; i++) acc[i] = 0.f;
    float bv = bo[t];

    for (int k4 = 0; k4 < K4; k4++) {
        int k = k4 * 4;
        float w0 = __ldg(&Wo[(k + 0) * DD + t]);
        float w1 = __ldg(&Wo[(k + 1) * DD + t]);
        float w2 = __ldg(&Wo[(k + 2) * DD + t]);
        float w3 = __ldg(&Wo[(k + 3) * DD + t]);
        #pragma unroll
        for (int i = 0; i < NB; i++) {
            float4 s = sh4[i * K4 + k4];
            acc[i] += s.x * w0;
            acc[i] += s.y * w1;
            acc[i] += s.z * w2;
            acc[i] += s.w * w3;
        }
    }

    #pragma unroll
    for (int i = 0; i < NB; i++) so[i * DD + t] = acc[i] + bv;
    __syncthreads();

    if (t < NB) {
        float s = 0.f;
        for (int j = 0; j < DD; j++) s += so[t * DD + j];
        float mu = s * (1.0f / DD);
        float s2 = 0.f;
        for (int j = 0; j < DD; j++) {
            float d = so[t * DD + j] - mu;
            s2 += d * d;
        }
        mu_s[t] = mu;
        rs_s[t] = rsqrtf(s2 * (1.0f / DD) + 1e-5f);
    }
    __syncthreads();

    #pragma unroll
    for (int i = 0; i < NB; i++)
        out[(size_t)(n0 + i) * DD + t] = (so[i * DD + t] - mu_s[i]) * rs_s[i];
}

// ---------------------------------------------------------------------------
// Launch (two-stream fork for CSR vs layer-1 GEMM; persistent GEMM grids).
// ---------------------------------------------------------------------------
extern "C" void kernel_launch(void* const* d_in, const int* in_sizes, int n_in,
                              void* d_out, int out_size)
{
    const float* in_feat = (const float*)d_in[0];
    const int*   src     = (const int*)d_in[1];
    const int*   dst     = (const int*)d_in[2];
    const float* W1      = (const float*)d_in[3];
    const float* al1     = (const float*)d_in[4];
    const float* ar1     = (const float*)d_in[5];
    const float* b1      = (const float*)d_in[6];
    const float* Whp     = (const float*)d_in[7];
    const float* alh     = (const float*)d_in[8];
    const float* arh     = (const float*)d_in[9];
    const float* bh      = (const float*)d_in[10];
    const float* Wo      = (const float*)d_in[11];
    const float* bo      = (const float*)d_in[12];
    float* out = (float*)d_out;

    static cudaStream_t s2 = nullptr;
    static cudaEvent_t ev_fork = nullptr, ev_join = nullptr;
    if (s2 == nullptr) {
        cudaStreamCreateWithFlags(&s2, cudaStreamNonBlocking);
        cudaEventCreateWithFlags(&ev_fork, cudaEventDisableTiming);
        cudaEventCreateWithFlags(&ev_join, cudaEventDisableTiming);
    }

    // smem bytes: (4*64*ASp + 2*K2*WSp) * 4   (A double-buffered hi+lo)
    const int SMEM1 = (4 * 64 * (IN_F / 2 + 4) + 2 * (IN_F / 2) * 264) * 4; // 204800
    const int SMEMH = (4 * 64 * (DD / 2 + 4) + 2 * (DD / 2) * 264) * 4;     // 104448
    cudaFuncSetAttribute((const void*)gemm_mma_k<IN_F, false>,
                         cudaFuncAttributeMaxDynamicSharedMemorySize, SMEM1);
    cudaFuncSetAttribute((const void*)gemm_mma_k<DD, true>,
                         cudaFuncAttributeMaxDynamicSharedMemorySize, SMEMH);

    const int G1 = 148;                // persistent, 1 block/SM (200 KB smem)
    const int GH = 296;                // persistent, 2 blocks/SM (104 KB smem)
    const int GAGG = (NN + 7) / 8;     // 6250 blocks (8 nodes/block)

    // layer W offsets (uint32 units, k-pair packed)
    const int WF0 = 0, WF1 = 16384, WF2 = 16384 + 8192, WF3 = 16384 + 2 * 8192;

    // Weight split (all layers) + g_cur zeroing, one launch (main stream).
    split_zero_k<<<(40960 + NN + 255) / 256, 256>>>(W1, Whp);
    cudaEventRecord(ev_fork, 0);

    // CSR chain on stream s2 (depends only on g_cur zeroing)
    cudaStreamWaitEvent(s2, ev_fork, 0);
    hist_k<<<(EE + 255) / 256, 256, 0, s2>>>(dst);
    scan1_k<<<SCAN_BLOCKS, 1024, 0, s2>>>();
    scan2_k<<<SCAN_BLOCKS, 1024, 0, s2>>>();
    scatter_k<<<(EE + 255) / 256, 256, 0, s2>>>(src, dst);
    cudaEventRecord(ev_join, s2);

    // Layer-1 GEMM on main stream, concurrent with CSR chain
    gemm_mma_k<IN_F, false><<<G1, 256, SMEM1>>>(in_feat, WF0, al1, ar1);

    // Join: edge_agg needs both CSR and feat
    cudaStreamWaitEvent(0, ev_join, 0);
    edge_agg_w<true><<<GAGG, 256>>>(b1);

    // Hidden layers 0,1 (mean) — A pre-split by previous agg
    gemm_mma_k<DD, true><<<GH, 256, SMEMH>>>(nullptr, WF1, alh + 0 * HD, arh + 0 * HD);
    edge_agg_w<true><<<GAGG, 256>>>(bh + 0 * HD);
    gemm_mma_k<DD, true><<<GH, 256, SMEMH>>>(nullptr, WF2, alh + 1 * HD, arh + 1 * HD);
    edge_agg_w<true><<<GAGG, 256>>>(bh + 1 * HD);

    // Hidden layer 2 (full [N,H,D] fp16 output)
    gemm_mma_k<DD, true><<<GH, 256, SMEMH>>>(nullptr, WF3, alh + 2 * HD, arh + 2 * HD);
    edge_agg_w<false><<<GAGG, 256>>>(bh + 2 * HD);

    // Final linear + LayerNorm -> d_out
    final_ln_k<<<NN / 16, 64>>>(Wo, bo, out);
}

// round 16
// speedup vs baseline: 1.3554x; 1.1596x over previous
#include <cuda_runtime.h>
#include <cuda_bf16.h>
#include <cuda_fp16.h>
#include <cstdint>

// Problem constants (match reference_code)
#define NN 50000      // nodes
#define EE 800000     // edges
#define IN_F 128
#define DD 64
#define HH 4
#define HD 256        // H*D
#define NEG_SLOPE 0.2f

#define SCAN_CHUNK 4096
#define SCAN_BLOCKS ((NN + SCAN_CHUNK - 1) / SCAN_CHUNK)   // 13
#define NTILES ((NN + 63) / 64)                            // 782

// ---------------------------------------------------------------------------
// Scratch (static __device__ arrays — no allocation allowed)
// ---------------------------------------------------------------------------
__device__ __half   g_feat_h[(size_t)NN * HD]; // projected features [N,256] fp16
__device__ __half   g_h16[(size_t)NN * HD];    // last-layer io buffer (fp16)
__device__ uint32_t g_Ah[(size_t)NN * 32];     // hidden activations bf16-hi (k-pairs)
__device__ uint32_t g_Al[(size_t)NN * 32];     // hidden activations bf16-lo
__device__ float    g_el[(size_t)NN * HH];
__device__ float    g_er[(size_t)NN * HH];
__device__ int      g_rowptr[NN + 1];
__device__ int      g_cur[NN];
__device__ int      g_csr[EE];                 // src per CSR slot (sorted by dst)
__device__ int      g_bsum[SCAN_BLOCKS];       // scan phase-1 block totals
// W bf16 hi/lo, k-pairs packed, ALL layers: L0 64*256, L1-3 each 32*256
__device__ uint32_t g_Wph[16384 + 3 * 8192];
__device__ uint32_t g_Wpl[16384 + 3 * 8192];
// Wo fp16 hi/lo, k-pairs packed: 128 k2-rows x 64 cols
__device__ uint32_t g_Woh[8192];
__device__ uint32_t g_Wol[8192];

// ---------------------------------------------------------------------------
// CSR build: (zero fused into split) -> histogram -> scan1 -> scan2 -> scatter
// ---------------------------------------------------------------------------
__global__ void hist_k(const int* __restrict__ dst) {
    int e = blockIdx.x * blockDim.x + threadIdx.x;
    if (e < EE) atomicAdd(&g_cur[dst[e]], 1);
}

__global__ void __launch_bounds__(1024) scan1_k() {
    __shared__ int ws[32];
    int t = threadIdx.x, lane = t & 31, wid = t >> 5;
    int i0 = blockIdx.x * SCAN_CHUNK + t * 4;
    int4 v = make_int4(0, 0, 0, 0);
    if (i0 < NN) {
        v = *(const int4*)&g_cur[i0];
        *(int4*)&g_cur[i0] = make_int4(0, 0, 0, 0);
    }
    int tsum = v.x + v.y + v.z + v.w;
    int x = tsum;
    #pragma unroll
    for (int o = 1; o < 32; o <<= 1) {
        int y = __shfl_up_sync(0xffffffffu, x, o);
        if (lane >= o) x += y;
    }
    if (lane == 31) ws[wid] = x;
    __syncthreads();
    if (wid == 0) {
        int y = ws[lane];
        #pragma unroll
        for (int o = 1; o < 32; o <<= 1) {
            int z = __shfl_up_sync(0xffffffffu, y, o);
            if (lane >= o) y += z;
        }
        ws[lane] = y;
    }
    __syncthreads();
    int excl = x - tsum + (wid ? ws[wid - 1] : 0);
    if (i0 < NN) {
        g_rowptr[i0]     = excl;
        g_rowptr[i0 + 1] = excl + v.x;
        g_rowptr[i0 + 2] = excl + v.x + v.y;
        g_rowptr[i0 + 3] = excl + v.x + v.y + v.z;
    }
    if (t == 1023) g_bsum[blockIdx.x] = ws[31];
}

__global__ void __launch_bounds__(1024) scan2_k() {
    __shared__ int s_off, s_tot;
    int t = threadIdx.x, b = blockIdx.x;
    if (t == 0) {
        int off = 0, tot = 0;
        #pragma unroll
        for (int j = 0; j < SCAN_BLOCKS; j++) {
            int v = g_bsum[j];
            if (j < b) off += v;
            tot += v;
        }
        s_off = off; s_tot = tot;
    }
    __syncthreads();
    int off = s_off;
    int i0 = b * SCAN_CHUNK + t * 4;
    if (off != 0 && i0 < NN) {
        int4 r = *(int4*)&g_rowptr[i0];
        r.x += off; r.y += off; r.z += off; r.w += off;
        *(int4*)&g_rowptr[i0] = r;
    }
    if (b == 0 && t == 0) g_rowptr[NN] = s_tot;
}

__global__ void scatter_k(const int* __restrict__ src, const int* __restrict__ dst) {
    int e = blockIdx.x * blockDim.x + threadIdx.x;
    if (e < EE) {
        int d = dst[e];
        int pos = g_rowptr[d] + atomicAdd(&g_cur[d], 1);
        g_csr[pos] = src[e];
    }
}

// ---------------------------------------------------------------------------
// split helpers (bf16 for conv weights/activations, fp16 for Wo)
// ---------------------------------------------------------------------------
__device__ __forceinline__ void bf16_split(float v, __nv_bfloat16& h, __nv_bfloat16& l) {
    h = __float2bfloat16_rn(v);
    l = __float2bfloat16_rn(v - __bfloat162float(h));
}
__device__ __forceinline__ uint32_t pack_bf16(__nv_bfloat16 lo, __nv_bfloat16 hi) {
    __nv_bfloat162 p = __halves2bfloat162(lo, hi);
    return *reinterpret_cast<uint32_t*>(&p);
}
__device__ __forceinline__ uint32_t split_pack_pair(float v0, float v1,
                                                    uint32_t& lo_out) {
    __nv_bfloat16 h0, l0, h1, l1;
    bf16_split(v0, h0, l0);
    bf16_split(v1, h1, l1);
    lo_out = pack_bf16(l0, l1);
    return pack_bf16(h0, h1);
}
__device__ __forceinline__ uint32_t split_pack_pair_f16(float v0, float v1,
                                                        uint32_t& lo_out) {
    __half h0 = __float2half_rn(v0);
    __half l0 = __float2half_rn(v0 - __half2float(h0));
    __half h1 = __float2half_rn(v1);
    __half l1 = __float2half_rn(v1 - __half2float(h1));
    __half2 lo = __halves2half2(l0, l1);
    __half2 hi = __halves2half2(h0, h1);
    lo_out = *(uint32_t*)&lo;
    return *(uint32_t*)&hi;
}

// Split ALL conv weights (bf16) + Wo (fp16), one launch, AND zero g_cur.
__global__ void split_zero_k(const float* __restrict__ W1,
                             const float* __restrict__ Whp,
                             const float* __restrict__ Wo)
{
    int tid = blockIdx.x * blockDim.x + threadIdx.x;
    if (tid >= 49152) {
        int z = tid - 49152;
        if (z < NN) g_cur[z] = 0;
        return;
    }
    if (tid >= 40960) {                     // Wo: 128 k2-rows x 64 cols, fp16 split
        int local = tid - 40960;
        int k2 = local >> 6, n = local & 63;
        uint32_t lo;
        uint32_t hi = split_pack_pair_f16(Wo[(2 * k2) * DD + n],
                                          Wo[(2 * k2 + 1) * DD + n], lo);
        g_Woh[local] = hi;
        g_Wol[local] = lo;
        return;
    }
    const float* W;
    int local, off;
    if (tid < 16384) {                      // layer 0, K2=64
        W = W1; local = tid; off = 0;
    } else {
        int t2 = tid - 16384;
        int layer = t2 >> 13;               // 0..2
        W = Whp + (size_t)layer * DD * HD;
        local = t2 & 8191;
        off = 16384 + layer * 8192;
    }
    int k2 = local >> 8, n = local & 255;
    uint32_t lo;
    uint32_t hi = split_pack_pair(W[(2 * k2) * 256 + n],
                                  W[(2 * k2 + 1) * 256 + n], lo);
    g_Wph[off + local] = hi;
    g_Wpl[off + local] = lo;
}

// ---------------------------------------------------------------------------
// mma wrappers
// ---------------------------------------------------------------------------
__device__ __forceinline__ void mma_bf16(float* c, const uint32_t* a,
                                         uint32_t b0, uint32_t b1)
{
    asm volatile(
        "mma.sync.aligned.m16n8k16.row.col.f32.bf16.bf16.f32 "
        "{%0,%1,%2,%3}, {%4,%5,%6,%7}, {%8,%9}, {%0,%1,%2,%3};"
        : "+f"(c[0]), "+f"(c[1]), "+f"(c[2]), "+f"(c[3])
        : "r"(a[0]), "r"(a[1]), "r"(a[2]), "r"(a[3]), "r"(b0), "r"(b1));
}
__device__ __forceinline__ void mma_f16(float* c, const uint32_t* a,
                                        uint32_t b0, uint32_t b1)
{
    asm volatile(
        "mma.sync.aligned.m16n8k16.row.col.f32.f16.f16.f32 "
        "{%0,%1,%2,%3}, {%4,%5,%6,%7}, {%8,%9}, {%0,%1,%2,%3};"
        : "+f"(c[0]), "+f"(c[1]), "+f"(c[2]), "+f"(c[3])
        : "r"(a[0]), "r"(a[1]), "r"(a[2]), "r"(a[3]), "r"(b0), "r"(b1));
}

// ---------------------------------------------------------------------------
// Persistent bf16 3-term tensor-core GEMM + fused attention coefficients.
// D = Ah*Wh + Ah*Wl + Al*Wh. W staged in smem ONCE per block; tiles strided
// by gridDim with double-buffered A, ONE __syncthreads per tile.
// ---------------------------------------------------------------------------
template <int K, bool PRESPLIT>
__global__ void __launch_bounds__(256) gemm_mma_k(
    const float* __restrict__ hin, int w_off,
    const float* __restrict__ al, const float* __restrict__ ar)
{
    constexpr int K2  = K / 2;
    constexpr int ASp = K2 + 4;   // ≡ 4 (mod 32): A frag loads conflict-free
    constexpr int WSp = 264;      // ≡ 8 (mod 32): B frag loads conflict-free
    constexpr int ABUF = 64 * ASp;
    extern __shared__ uint32_t smu[];
    uint32_t* sAh = smu;                         // 2 bufs x 64*ASp
    uint32_t* sAl = sAh + 2 * ABUF;              // 2 bufs x 64*ASp
    uint32_t* sWh = sAl + 2 * ABUF;              // K2*WSp
    uint32_t* sWl = sWh + K2 * WSp;              // K2*WSp

    int t = threadIdx.x, lane = t & 31, wid = t >> 5;
    int wm = wid >> 2, wn = wid & 3;     // warp M-row, warp N-col (= head)
    int g = lane >> 2, q = lane & 3;     // groupID (row), quad lane
    int gdim = gridDim.x;

    // Stage full W once (hi/lo)
    for (int idx = t; idx < K2 * 256; idx += 256) {
        int k2 = idx >> 8, n = idx & 255;
        sWh[k2 * WSp + n] = g_Wph[w_off + idx];
        sWl[k2 * WSp + n] = g_Wpl[w_off + idx];
    }

    // Epilogue coefficients (tile-invariant)
    float alv[8][2], arv[8][2];
    #pragma unroll
    for (int j = 0; j < 8; j++) {
        int col = wn * 64 + j * 8 + 2 * q;
        alv[j][0] = al[col]; alv[j][1] = al[col + 1];
        arv[j][0] = ar[col]; arv[j][1] = ar[col + 1];
    }

    int buf = 0;
    for (int tile = blockIdx.x; tile < NTILES; tile += gdim, buf ^= 1) {
        int n0 = tile * 64;
        uint32_t* bAh = sAh + buf * ABUF;
        uint32_t* bAl = sAl + buf * ABUF;

        // Stage A into current buffer
        if (PRESPLIT) {
            for (int idx = t; idx < 64 * 8; idx += 256) {
                int r = idx >> 3, c4 = (idx & 7) * 4;
                uint4 h = make_uint4(0, 0, 0, 0), l = make_uint4(0, 0, 0, 0);
                if (n0 + r < NN) {
                    h = *(const uint4*)&g_Ah[(size_t)(n0 + r) * 32 + c4];
                    l = *(const uint4*)&g_Al[(size_t)(n0 + r) * 32 + c4];
                }
                *(uint4*)&bAh[r * ASp + c4] = h;
                *(uint4*)&bAl[r * ASp + c4] = l;
            }
        } else {
            for (int idx = t; idx < 64 * K2; idx += 256) {
                int r = idx / K2, k2 = idx % K2;
                float v0 = 0.f, v1 = 0.f;
                if (n0 + r < NN) {
                    float2 vv = *(const float2*)&hin[(size_t)(n0 + r) * K + 2 * k2];
                    v0 = vv.x; v1 = vv.y;
                }
                uint32_t lo;
                uint32_t hi = split_pack_pair(v0, v1, lo);
                bAh[r * ASp + k2] = hi;
                bAl[r * ASp + k2] = lo;
            }
        }
        __syncthreads();

        float c_[2][8][4];
        #pragma unroll
        for (int i = 0; i < 2; i++)
            #pragma unroll
            for (int j = 0; j < 8; j++)
                #pragma unroll
                for (int r = 0; r < 4; r++) c_[i][j][r] = 0.f;

        for (int ks = 0; ks < K / 16; ks++) {
            int k2b = ks * 8;
            uint32_t ah[2][4], alr[2][4];
            #pragma unroll
            for (int i = 0; i < 2; i++) {
                int r = wm * 32 + i * 16 + g;
                ah[i][0]  = bAh[r * ASp + k2b + q];
                ah[i][1]  = bAh[(r + 8) * ASp + k2b + q];
                ah[i][2]  = bAh[r * ASp + k2b + 4 + q];
                ah[i][3]  = bAh[(r + 8) * ASp + k2b + 4 + q];
                alr[i][0] = bAl[r * ASp + k2b + q];
                alr[i][1] = bAl[(r + 8) * ASp + k2b + q];
                alr[i][2] = bAl[r * ASp + k2b + 4 + q];
                alr[i][3] = bAl[(r + 8) * ASp + k2b + 4 + q];
            }
            #pragma unroll
            for (int j = 0; j < 8; j++) {
                int ncol = wn * 64 + j * 8 + g;
                uint32_t bh0 = sWh[(k2b + q) * WSp + ncol];
                uint32_t bh1 = sWh[(k2b + 4 + q) * WSp + ncol];
                uint32_t bl0 = sWl[(k2b + q) * WSp + ncol];
                uint32_t bl1 = sWl[(k2b + 4 + q) * WSp + ncol];
                #pragma unroll
                for (int i = 0; i < 2; i++) {
                    mma_bf16(c_[i][j], ah[i], bh0, bh1);
                    mma_bf16(c_[i][j], ah[i], bl0, bl1);
                    mma_bf16(c_[i][j], alr[i], bh0, bh1);
                }
            }
        }

        // Epilogue: store feat (fp16), fused el/er
        #pragma unroll
        for (int i = 0; i < 2; i++) {
            int rtop = n0 + wm * 32 + i * 16 + g;
            int rbot = rtop + 8;
            float plt = 0.f, prt = 0.f, plb = 0.f, prb = 0.f;
            #pragma unroll
            for (int j = 0; j < 8; j++) {
                int cb = wn * 64 + j * 8 + 2 * q;
                if (rtop < NN)
                    *(__half2*)&g_feat_h[(size_t)rtop * HD + cb] =
                        __floats2half2_rn(c_[i][j][0], c_[i][j][1]);
                if (rbot < NN)
                    *(__half2*)&g_feat_h[(size_t)rbot * HD + cb] =
                        __floats2half2_rn(c_[i][j][2], c_[i][j][3]);
                plt += c_[i][j][0] * alv[j][0] + c_[i][j][1] * alv[j][1];
                prt += c_[i][j][0] * arv[j][0] + c_[i][j][1] * arv[j][1];
                plb += c_[i][j][2] * alv[j][0] + c_[i][j][3] * alv[j][1];
                prb += c_[i][j][2] * arv[j][0] + c_[i][j][3] * arv[j][1];
            }
            #pragma unroll
            for (int o = 1; o <= 2; o <<= 1) {
                plt += __shfl_xor_sync(0xffffffffu, plt, o);
                prt += __shfl_xor_sync(0xffffffffu, prt, o);
                plb += __shfl_xor_sync(0xffffffffu, plb, o);
                prb += __shfl_xor_sync(0xffffffffu, prb, o);
            }
            if (q == 0) {
                if (rtop < NN) { g_el[rtop * HH + wn] = plt; g_er[rtop * HH + wn] = prt; }
                if (rbot < NN) { g_el[rbot * HH + wn] = plb; g_er[rbot * HH + wn] = prb; }
            }
        }
    }
}

// ---------------------------------------------------------------------------
// Warp-per-node edge softmax + aggregation (R15 form — best measured).
// ---------------------------------------------------------------------------
__device__ __forceinline__ float lrelu(float e) {
    return e > 0.f ? e : NEG_SLOPE * e;
}
__device__ __forceinline__ void acc_edge(float* acc, float w, uint4 f) {
    float2 p0 = __half22float2(*(const __half2*)&f.x);
    float2 p1 = __half22float2(*(const __half2*)&f.y);
    float2 p2 = __half22float2(*(const __half2*)&f.z);
    float2 p3 = __half22float2(*(const __half2*)&f.w);
    acc[0] += w * p0.x; acc[1] += w * p0.y;
    acc[2] += w * p1.x; acc[3] += w * p1.y;
    acc[4] += w * p2.x; acc[5] += w * p2.y;
    acc[6] += w * p3.x; acc[7] += w * p3.y;
}

template <bool MEAN>
__global__ void __launch_bounds__(256) edge_agg_w(const float* __restrict__ b)
{
    __shared__ float s_w_all[8][HH][33];
    __shared__ int   s_src_all[8][32];

    int t = threadIdx.x, lane = t & 31, wid = t >> 5;
    int n = blockIdx.x * 8 + wid;
    if (n >= NN) return;

    float (*s_w)[33] = s_w_all[wid];
    int* s_src = s_src_all[wid];

    int rb  = g_rowptr[n];
    int deg = g_rowptr[n + 1] - rb;

    int h = lane >> 3;
    float acc[8];
    #pragma unroll
    for (int i = 0; i < 8; i++) acc[i] = 0.f;

    const uint4* fb = (const uint4*)g_feat_h;

    if (deg > 0 && deg <= 32) {
        float4 er4 = *(const float4*)(g_er + n * HH);
        float e0 = -1e30f, e1 = -1e30f, e2 = -1e30f, e3 = -1e30f;
        if (lane < deg) {
            int sn = g_csr[rb + lane];
            s_src[lane] = sn;
            float4 el4 = *(const float4*)(g_el + sn * HH);
            e0 = lrelu(el4.x + er4.x);
            e1 = lrelu(el4.y + er4.y);
            e2 = lrelu(el4.z + er4.z);
            e3 = lrelu(el4.w + er4.w);
        }
        float m0 = e0, m1 = e1, m2 = e2, m3 = e3;
        #pragma unroll
        for (int o = 16; o; o >>= 1) {
            m0 = fmaxf(m0, __shfl_xor_sync(0xffffffffu, m0, o));
            m1 = fmaxf(m1, __shfl_xor_sync(0xffffffffu, m1, o));
            m2 = fmaxf(m2, __shfl_xor_sync(0xffffffffu, m2, o));
            m3 = fmaxf(m3, __shfl_xor_sync(0xffffffffu, m3, o));
        }
        float w0 = 0.f, w1 = 0.f, w2 = 0.f, w3 = 0.f;
        if (lane < deg) {
            w0 = __expf(e0 - m0);
            w1 = __expf(e1 - m1);
            w2 = __expf(e2 - m2);
            w3 = __expf(e3 - m3);
        }
        float s0 = w0, s1 = w1, s2 = w2, s3 = w3;
        #pragma unroll
        for (int o = 16; o; o >>= 1) {
            s0 += __shfl_xor_sync(0xffffffffu, s0, o);
            s1 += __shfl_xor_sync(0xffffffffu, s1, o);
            s2 += __shfl_xor_sync(0xffffffffu, s2, o);
            s3 += __shfl_xor_sync(0xffffffffu, s3, o);
        }
        if (lane < deg) {
            s_w[0][lane] = w0 / s0;
            s_w[1][lane] = w1 / s1;
            s_w[2][lane] = w2 / s2;
            s_w[3][lane] = w3 / s3;
        }
        __syncwarp();

        int j = 0;
        for (; j + 4 <= deg; j += 4) {
            int   sn0 = s_src[j],     sn1 = s_src[j + 1];
            int   sn2 = s_src[j + 2], sn3 = s_src[j + 3];
            float w0_ = s_w[h][j],     w1_ = s_w[h][j + 1];
            float w2_ = s_w[h][j + 2], w3_ = s_w[h][j + 3];
            uint4 f0 = fb[(size_t)sn0 * 32 + lane];
            uint4 f1 = fb[(size_t)sn1 * 32 + lane];
            uint4 f2 = fb[(size_t)sn2 * 32 + lane];
            uint4 f3 = fb[(size_t)sn3 * 32 + lane];
            acc_edge(acc, w0_, f0);
            acc_edge(acc, w1_, f1);
            acc_edge(acc, w2_, f2);
            acc_edge(acc, w3_, f3);
        }
        for (; j < deg; j++) {
            uint4 f = fb[(size_t)s_src[j] * 32 + lane];
            acc_edge(acc, s_w[h][j], f);
        }
    } else if (deg > 32) {
        float er_h = g_er[n * HH + h];
        float m = -1e30f;
        for (int j = 0; j < deg; j++) {
            int sn = g_csr[rb + j];
            m = fmaxf(m, lrelu(g_el[sn * HH + h] + er_h));
        }
        float s = 0.f;
        for (int j = 0; j < deg; j++) {
            int sn = g_csr[rb + j];
            s += __expf(lrelu(g_el[sn * HH + h] + er_h) - m);
        }
        float inv = 1.0f / s;
        for (int j = 0; j < deg; j++) {
            int sn = g_csr[rb + j];
            float w = __expf(lrelu(g_el[sn * HH + h] + er_h) - m) * inv;
            uint4 f = fb[(size_t)sn * 32 + lane];
            acc_edge(acc, w, f);
        }
    }

    if (MEAN) {
        #pragma unroll
        for (int o = 8; o <= 16; o <<= 1)
            #pragma unroll
            for (int i = 0; i < 8; i++)
                acc[i] += __shfl_down_sync(0xffffffffu, acc[i], o);
        if (lane < 8) {
            int d0 = lane * 8;
            float r[8];
            #pragma unroll
            for (int i = 0; i < 8; i++) {
                int d = d0 + i;
                r[i] = 0.25f * (acc[i] + b[d] + b[DD + d] + b[2 * DD + d] + b[3 * DD + d]);
            }
            uint32_t hi[4], lo[4];
            #pragma unroll
            for (int p = 0; p < 4; p++)
                hi[p] = split_pack_pair(r[2 * p], r[2 * p + 1], lo[p]);
            *(uint4*)&g_Ah[(size_t)n * 32 + lane * 4] =
                make_uint4(hi[0], hi[1], hi[2], hi[3]);
            *(uint4*)&g_Al[(size_t)n * 32 + lane * 4] =
                make_uint4(lo[0], lo[1], lo[2], lo[3]);
        }
    } else {
        int d0 = lane * 8;
        __half2 r[4];
        #pragma unroll
        for (int i = 0; i < 4; i++)
            r[i] = __floats2half2_rn(acc[2 * i] + b[d0 + 2 * i],
                                     acc[2 * i + 1] + b[d0 + 2 * i + 1]);
        *(uint2*)&g_h16[(size_t)n * HD + d0] =
            make_uint2(*(uint32_t*)&r[0], *(uint32_t*)&r[1]);
        *(uint2*)&g_h16[(size_t)n * HD + d0 + 4] =
            make_uint2(*(uint32_t*)&r[2], *(uint32_t*)&r[3]);
    }
}

// ---------------------------------------------------------------------------
// Final Linear(256->64) + LayerNorm via fp16 tensor-core mma.
// Tile: 64 nodes x 64 outputs; 8 warps = 2(M: m32) x 4(N: n16).
// D = A*Woh + A*Wol (A = g_h16 fp16 k-pairs, Wo fp16 2-term split).
// LN fused: C+bias -> smem (aliased over A), warp-per-8-rows reduction.
// ---------------------------------------------------------------------------
__global__ void __launch_bounds__(256) final_mma_k(
    const float* __restrict__ bo, float* __restrict__ out)
{
    constexpr int ASp = 132;   // uint32 stride for A (128+4, ≡4 mod 32)
    constexpr int WSp = 72;    // uint32 stride for W (64+8,  ≡8 mod 32)
    constexpr int SOp = 66;    // float stride for LN staging
    extern __shared__ uint32_t smf[];
    uint32_t* sA  = smf;                 // 64*132 = 8448 (aliased by so later)
    uint32_t* sWh = sA + 64 * ASp;       // 128*72 = 9216
    uint32_t* sWl = sWh + 128 * WSp;     // 128*72
    float*    so  = (float*)smf;         // 64*66 = 4224 floats (fits in sA)

    int t = threadIdx.x, lane = t & 31, wid = t >> 5;
    int wm = wid >> 2, wn = wid & 3;
    int g = lane >> 2, q = lane & 3;
    int n0 = blockIdx.x * 64;

    // Stage A (fp16 k-pairs direct from g_h16), zero-fill rows >= NN
    const uint32_t* hrow = (const uint32_t*)g_h16;
    for (int idx = t; idx < 64 * 128; idx += 256) {
        int r = idx >> 7, k2 = idx & 127;
        uint32_t v = 0;
        if (n0 + r < NN) v = hrow[(size_t)(n0 + r) * 128 + k2];
        sA[r * ASp + k2] = v;
    }
    // Stage Wo (hi/lo)
    for (int idx = t; idx < 128 * 64; idx += 256) {
        int k2 = idx >> 6, n = idx & 63;
        sWh[k2 * WSp + n] = g_Woh[idx];
        sWl[k2 * WSp + n] = g_Wol[idx];
    }
    __syncthreads();

    float c_[2][2][4];
    #pragma unroll
    for (int i = 0; i < 2; i++)
        #pragma unroll
        for (int j = 0; j < 2; j++)
            #pragma unroll
            for (int r = 0; r < 4; r++) c_[i][j][r] = 0.f;

    for (int ks = 0; ks < 16; ks++) {
        int k2b = ks * 8;
        uint32_t a[2][4];
        #pragma unroll
        for (int i = 0; i < 2; i++) {
            int r = wm * 32 + i * 16 + g;
            a[i][0] = sA[r * ASp + k2b + q];
            a[i][1] = sA[(r + 8) * ASp + k2b + q];
            a[i][2] = sA[r * ASp + k2b + 4 + q];
            a[i][3] = sA[(r + 8) * ASp + k2b + 4 + q];
        }
        #pragma unroll
        for (int j = 0; j < 2; j++) {
            int ncol = wn * 16 + j * 8 + g;
            uint32_t bh0 = sWh[(k2b + q) * WSp + ncol];
            uint32_t bh1 = sWh[(k2b + 4 + q) * WSp + ncol];
            uint32_t bl0 = sWl[(k2b + q) * WSp + ncol];
            uint32_t bl1 = sWl[(k2b + 4 + q) * WSp + ncol];
            #pragma unroll
            for (int i = 0; i < 2; i++) {
                mma_f16(c_[i][j], a[i], bh0, bh1);
                mma_f16(c_[i][j], a[i], bl0, bl1);
            }
        }
    }
    __syncthreads();   // everyone done reading sA before aliasing it as so

    // C + bias -> smem
    #pragma unroll
    for (int i = 0; i < 2; i++) {
        int rt = wm * 32 + i * 16 + g;
        #pragma unroll
        for (int j = 0; j < 2; j++) {
            int cb = wn * 16 + j * 8 + 2 * q;
            float b0 = __ldg(&bo[cb]), b1 = __ldg(&bo[cb + 1]);
            so[rt * SOp + cb]           = c_[i][j][0] + b0;
            so[rt * SOp + cb + 1]       = c_[i][j][1] + b1;
            so[(rt + 8) * SOp + cb]     = c_[i][j][2] + b0;
            so[(rt + 8) * SOp + cb + 1] = c_[i][j][3] + b1;
        }
    }
    __syncthreads();

    // LayerNorm: warp wid handles rows 8*wid .. 8*wid+7
    for (int rr = wid * 8; rr < wid * 8 + 8; rr++) {
        float v0 = so[rr * SOp + 2 * lane];
        float v1 = so[rr * SOp + 2 * lane + 1];
        float s = v0 + v1;
        #pragma unroll
        for (int o = 16; o; o >>= 1) s += __shfl_xor_sync(0xffffffffu, s, o);
        float mu = s * (1.0f / DD);
        float d0 = v0 - mu, d1 = v1 - mu;
        float s2 = d0 * d0 + d1 * d1;
        #pragma unroll
        for (int o = 16; o; o >>= 1) s2 += __shfl_xor_sync(0xffffffffu, s2, o);
        float rs = rsqrtf(s2 * (1.0f / DD) + 1e-5f);
        int grow = n0 + rr;
        if (grow < NN)
            *(float2*)&out[(size_t)grow * DD + 2 * lane] =
                make_float2(d0 * rs, d1 * rs);
    }
}

// ---------------------------------------------------------------------------
// Launch (two-stream fork for CSR vs layer-1 GEMM; persistent GEMM grids).
// ---------------------------------------------------------------------------
extern "C" void kernel_launch(void* const* d_in, const int* in_sizes, int n_in,
                              void* d_out, int out_size)
{
    const float* in_feat = (const float*)d_in[0];
    const int*   src     = (const int*)d_in[1];
    const int*   dst     = (const int*)d_in[2];
    const float* W1      = (const float*)d_in[3];
    const float* al1     = (const float*)d_in[4];
    const float* ar1     = (const float*)d_in[5];
    const float* b1      = (const float*)d_in[6];
    const float* Whp     = (const float*)d_in[7];
    const float* alh     = (const float*)d_in[8];
    const float* arh     = (const float*)d_in[9];
    const float* bh      = (const float*)d_in[10];
    const float* Wo      = (const float*)d_in[11];
    const float* bo      = (const float*)d_in[12];
    float* out = (float*)d_out;

    static cudaStream_t s2 = nullptr;
    static cudaEvent_t ev_fork = nullptr, ev_join = nullptr;
    if (s2 == nullptr) {
        cudaStreamCreateWithFlags(&s2, cudaStreamNonBlocking);
        cudaEventCreateWithFlags(&ev_fork, cudaEventDisableTiming);
        cudaEventCreateWithFlags(&ev_join, cudaEventDisableTiming);
    }

    // smem bytes: (4*64*ASp + 2*K2*WSp) * 4   (A double-buffered hi+lo)
    const int SMEM1 = (4 * 64 * (IN_F / 2 + 4) + 2 * (IN_F / 2) * 264) * 4; // 204800
    const int SMEMH = (4 * 64 * (DD / 2 + 4) + 2 * (DD / 2) * 264) * 4;     // 104448
    const int SMEMF = (64 * 132 + 2 * 128 * 72) * 4;                        // 107520
    cudaFuncSetAttribute((const void*)gemm_mma_k<IN_F, false>,
                         cudaFuncAttributeMaxDynamicSharedMemorySize, SMEM1);
    cudaFuncSetAttribute((const void*)gemm_mma_k<DD, true>,
                         cudaFuncAttributeMaxDynamicSharedMemorySize, SMEMH);
    cudaFuncSetAttribute((const void*)final_mma_k,
                         cudaFuncAttributeMaxDynamicSharedMemorySize, SMEMF);

    const int G1 = 148;                // persistent, 1 block/SM (200 KB smem)
    const int GH = 296;                // persistent, 2 blocks/SM (104 KB smem)
    const int GAGG = (NN + 7) / 8;     // 6250 blocks (8 nodes/block)

    // layer W offsets (uint32 units, k-pair packed)
    const int WF0 = 0, WF1 = 16384, WF2 = 16384 + 8192, WF3 = 16384 + 2 * 8192;

    // Weight split (all layers + Wo) + g_cur zeroing, one launch (main stream).
    split_zero_k<<<(49152 + NN + 255) / 256, 256>>>(W1, Whp, Wo);
    cudaEventRecord(ev_fork, 0);

    // CSR chain on stream s2 (depends only on g_cur zeroing)
    cudaStreamWaitEvent(s2, ev_fork, 0);
    hist_k<<<(EE + 255) / 256, 256, 0, s2>>>(dst);
    scan1_k<<<SCAN_BLOCKS, 1024, 0, s2>>>();
    scan2_k<<<SCAN_BLOCKS, 1024, 0, s2>>>();
    scatter_k<<<(EE + 255) / 256, 256, 0, s2>>>(src, dst);
    cudaEventRecord(ev_join, s2);

    // Layer-1 GEMM on main stream, concurrent with CSR chain
    gemm_mma_k<IN_F, false><<<G1, 256, SMEM1>>>(in_feat, WF0, al1, ar1);

    // Join: edge_agg needs both CSR and feat
    cudaStreamWaitEvent(0, ev_join, 0);
    edge_agg_w<true><<<GAGG, 256>>>(b1);

    // Hidden layers 0,1 (mean) — A pre-split by previous agg
    gemm_mma_k<DD, true><<<GH, 256, SMEMH>>>(nullptr, WF1, alh + 0 * HD, arh + 0 * HD);
    edge_agg_w<true><<<GAGG, 256>>>(bh + 0 * HD);
    gemm_mma_k<DD, true><<<GH, 256, SMEMH>>>(nullptr, WF2, alh + 1 * HD, arh + 1 * HD);
    edge_agg_w<true><<<GAGG, 256>>>(bh + 1 * HD);

    // Hidden layer 2 (full [N,H,D] fp16 output)
    gemm_mma_k<DD, true><<<GH, 256, SMEMH>>>(nullptr, WF3, alh + 2 * HD, arh + 2 * HD);
    edge_agg_w<false><<<GAGG, 256>>>(bh + 2 * HD);

    // Final linear (tensor core) + LayerNorm -> d_out
    final_mma_k<<<NTILES, 256, SMEMF>>>(bo, out);
}